// round 1
// baseline (speedup 1.0000x reference)
#include <cuda_runtime.h>
#include <cuda_bf16.h>
#include <cstdint>

#define D       128
#define TWOD    256
#define N_INIT  100000
#define LVLS    64
#define MM      4096
#define N_RULES 256
#define N_TOT   (N_INIT + LVLS * MM)

#define NG 16                 // node slots per compute group
// shared layout sizes (floats)
#define SW_FLOATS (TWOD * D)          // 32768 floats = 128 KB
#define SX_FLOATS (TWOD * NG)         // 4096 floats = 16 KB
#define LIST_BYTES (MM * 2)           // 8 KB (unsigned short)
#define LEVEL_SMEM (SW_FLOATS * 4 + SX_FLOATS * 4 + LIST_BYTES)

// ---------------- device scratch (no allocations allowed) ----------------
__device__ float  g_store[(size_t)N_TOT * D];   // ~185 MB node embedding store
__device__ double g_acc[8];                     // A, B, sumPos, sumNeg, posOK, negOK

// ---------------- init: axiom embeddings + zero accumulators ----------------
__global__ void init_kernel(const float* __restrict__ thax_table,
                            const float* __restrict__ sine_table,
                            const int*   __restrict__ init_thax,
                            const int*   __restrict__ init_sine)
{
    int idx = blockIdx.x * blockDim.x + threadIdx.x;
    if (blockIdx.x == 0 && threadIdx.x < 8) g_acc[threadIdx.x] = 0.0;
    int total = N_INIT * (D / 4);
    if (idx >= total) return;
    int n = idx >> 5;          // D/4 = 32 float4 per row
    int q = idx & 31;
    const float4* ta = (const float4*)(thax_table + (size_t)init_thax[n] * D);
    const float4* sa = (const float4*)(sine_table + (size_t)init_sine[n] * D);
    float4 a = ta[q], b = sa[q], o;
    o.x = a.x + b.x; o.y = a.y + b.y; o.z = a.z + b.z; o.w = a.w + b.w;
    ((float4*)(g_store + (size_t)n * D))[q] = o;
}

// ---------------- per-level rule-grouped MLP ----------------
// grid = 256 (one CTA per rule), block = 128 threads.
// smem: W[256][128] (rule weights), X[256][16] (k-major staged parent concat),
//       list of node ids for this rule.
__global__ __launch_bounds__(128, 1)
void level_kernel(int lvl,
                  const float* __restrict__ rule_W,
                  const float* __restrict__ rule_b,
                  const int*   __restrict__ parents,
                  const int*   __restrict__ rules)
{
    extern __shared__ float smem[];
    float*          sW    = smem;                       // [256*128]
    float*          sX    = smem + SW_FLOATS;           // [256*16], layout [i][slot]
    unsigned short* sList = (unsigned short*)(sX + SX_FLOATS);
    __shared__ int sCount;

    const int tid  = threadIdx.x;
    const int rule = blockIdx.x;

    // stage W[rule] into shared (128 KB)
    {
        const float4* wg  = (const float4*)(rule_W + (size_t)rule * SW_FLOATS);
        float4*       sW4 = (float4*)sW;
        #pragma unroll 8
        for (int k = tid; k < SW_FLOATS / 4; k += 128) sW4[k] = wg[k];
    }
    if (tid == 0) sCount = 0;
    __syncthreads();

    // find this rule's nodes in the level
    const int* lr = rules + lvl * MM;
    for (int m = tid; m < MM; m += 128) {
        if (lr[m] == rule) {
            int p = atomicAdd(&sCount, 1);
            sList[p] = (unsigned short)m;
        }
    }
    __syncthreads();
    const int count = sCount;
    if (count == 0) return;

    const int cg = tid & 31;   // column group: cols [cg*4, cg*4+4)
    const int ng = tid >> 5;   // node subgroup: slots [ng*4, ng*4+4)
    const float4 bias = ((const float4*)(rule_b + (size_t)rule * D))[cg];
    const int* lp = parents + (size_t)lvl * MM * 2;
    const float4* sW4 = (const float4*)sW;

    for (int g = 0; g < count; g += NG) {
        // ---- stage X: concat(parent0, parent1) for up to 16 nodes, k-major ----
        {
            int slot = tid & 15;          // node slot
            int seg  = tid >> 4;          // 0..7, each = 32 k-values
            int idx  = g + slot;
            if (idx < count) {
                int m = sList[idx];
                int p = lp[2 * m + (seg >> 2)];               // parent 0 or 1
                const float4* src = (const float4*)(g_store + (size_t)p * D + (seg & 3) * 32);
                int ib = seg * 32;
                #pragma unroll
                for (int j = 0; j < 8; j++) {
                    float4 v = src[j];
                    int i = ib + j * 4;
                    sX[(i + 0) * NG + slot] = v.x;
                    sX[(i + 1) * NG + slot] = v.y;
                    sX[(i + 2) * NG + slot] = v.z;
                    sX[(i + 3) * NG + slot] = v.w;
                }
            }
        }
        __syncthreads();

        // ---- 16x128 tile GEMM: thread computes 4 nodes x 4 cols ----
        float4 acc0 = {0.f,0.f,0.f,0.f};
        float4 acc1 = {0.f,0.f,0.f,0.f};
        float4 acc2 = {0.f,0.f,0.f,0.f};
        float4 acc3 = {0.f,0.f,0.f,0.f};
        #pragma unroll 4
        for (int i = 0; i < TWOD; i++) {
            float4 wv = sW4[i * 32 + cg];
            float4 xv = *(const float4*)&sX[i * NG + (ng << 2)];
            acc0.x += xv.x * wv.x; acc0.y += xv.x * wv.y; acc0.z += xv.x * wv.z; acc0.w += xv.x * wv.w;
            acc1.x += xv.y * wv.x; acc1.y += xv.y * wv.y; acc1.z += xv.y * wv.z; acc1.w += xv.y * wv.w;
            acc2.x += xv.z * wv.x; acc2.y += xv.z * wv.y; acc2.z += xv.z * wv.z; acc2.w += xv.z * wv.w;
            acc3.x += xv.w * wv.x; acc3.y += xv.w * wv.y; acc3.z += xv.w * wv.z; acc3.w += xv.w * wv.w;
        }

        // ---- epilogue: bias + ReLU + store ----
        float4 accs[4] = {acc0, acc1, acc2, acc3};
        #pragma unroll
        for (int j = 0; j < 4; j++) {
            int slot = (ng << 2) + j;
            int idx = g + slot;
            if (idx < count) {
                int m = sList[idx];
                float4 o;
                o.x = fmaxf(accs[j].x + bias.x, 0.f);
                o.y = fmaxf(accs[j].y + bias.y, 0.f);
                o.z = fmaxf(accs[j].z + bias.z, 0.f);
                o.w = fmaxf(accs[j].w + bias.w, 0.f);
                float* row = g_store + (size_t)(N_INIT + lvl * MM + m) * D;
                ((float4*)row)[cg] = o;
            }
        }
        __syncthreads();   // protect sX before next group's fill
    }
}

// ---------------- final reduction ----------------
__device__ __forceinline__ float softplusf(float x) {
    return fmaxf(x, 0.f) + log1pf(expf(-fabsf(x)));
}

__global__ void reduce_kernel(const float* __restrict__ eval_w,
                              const float* __restrict__ eval_b,
                              const float* __restrict__ pos_vals,
                              const float* __restrict__ neg_vals)
{
    __shared__ double part[6];
    const int lane = threadIdx.x & 31;
    const int wid  = threadIdx.x >> 5;
    const int warpsPerBlock = blockDim.x >> 5;
    const int gw  = blockIdx.x * warpsPerBlock + wid;
    const int nw  = gridDim.x * warpsPerBlock;

    const float4 ew = ((const float4*)eval_w)[lane];
    const float  eb = eval_b[0];

    double a = 0, b = 0, sp = 0, sn = 0, pok = 0, nok = 0;
    for (int row = gw; row < N_TOT; row += nw) {
        float4 v = ((const float4*)(g_store + (size_t)row * D))[lane];
        float s = v.x * ew.x + v.y * ew.y + v.z * ew.z + v.w * ew.w;
        #pragma unroll
        for (int o = 16; o; o >>= 1) s += __shfl_xor_sync(0xffffffffu, s, o);
        if (lane == 0) {
            float logit = s + eb;
            float pv = pos_vals[row], nv = neg_vals[row];
            a  += (double)(pv * softplusf(-logit));
            b  += (double)(nv * softplusf(logit));
            sp += (double)pv;
            sn += (double)nv;
            if (logit >= 0.f) pok += (double)pv; else nok += (double)nv;
        }
    }
    if (threadIdx.x < 6) part[threadIdx.x] = 0.0;
    __syncthreads();
    if (lane == 0) {
        atomicAdd(&part[0], a);  atomicAdd(&part[1], b);
        atomicAdd(&part[2], sp); atomicAdd(&part[3], sn);
        atomicAdd(&part[4], pok); atomicAdd(&part[5], nok);
    }
    __syncthreads();
    if (threadIdx.x < 6) atomicAdd(&g_acc[threadIdx.x], part[threadIdx.x]);
}

__global__ void finalize_kernel(float* out, int out_size)
{
    double A = g_acc[0], B = g_acc[1], P = g_acc[2], N = g_acc[3];
    double loss = (N / P) * A + B;
    if (out_size > 0) out[0] = (float)loss;
    if (out_size > 1) out[1] = (float)g_acc[4];
    if (out_size > 2) out[2] = (float)g_acc[5];
}

// ---------------- launch ----------------
extern "C" void kernel_launch(void* const* d_in, const int* in_sizes, int n_in,
                              void* d_out, int out_size)
{
    const float* thax_table = (const float*)d_in[0];
    const float* sine_table = (const float*)d_in[1];
    const float* rule_W     = (const float*)d_in[2];
    const float* rule_b     = (const float*)d_in[3];
    const float* eval_w     = (const float*)d_in[4];
    const float* eval_b     = (const float*)d_in[5];
    const float* pos_vals   = (const float*)d_in[6];
    const float* neg_vals   = (const float*)d_in[7];
    const int*   init_thax  = (const int*)d_in[8];
    const int*   init_sine  = (const int*)d_in[9];
    const int*   parents    = (const int*)d_in[10];
    const int*   rules      = (const int*)d_in[11];

    cudaFuncSetAttribute(level_kernel,
                         cudaFuncAttributeMaxDynamicSharedMemorySize, LEVEL_SMEM);

    {   // axiom embeddings + accumulator reset
        int total = N_INIT * (D / 4);
        int blocks = (total + 255) / 256;
        init_kernel<<<blocks, 256>>>(thax_table, sine_table, init_thax, init_sine);
    }

    for (int l = 0; l < LVLS; l++) {
        level_kernel<<<N_RULES, 128, LEVEL_SMEM>>>(l, rule_W, rule_b, parents, rules);
    }

    reduce_kernel<<<1184, 256>>>(eval_w, eval_b, pos_vals, neg_vals);
    finalize_kernel<<<1, 1>>>((float*)d_out, out_size);
}

// round 2
// speedup vs baseline: 1.9571x; 1.9571x over previous
#include <cuda_runtime.h>
#include <cuda_bf16.h>
#include <cstdint>

#define D       128
#define TWOD    256
#define N_INIT  100000
#define LVLS    64
#define MM      4096
#define N_RULES 256
#define N_TOT   (N_INIT + LVLS * MM)

#define XSTRIDE 260              // 256 + 4 pad: conflict-free A-frag LDS

// ---------------- device scratch (no allocations allowed) ----------------
__device__ float  g_store[(size_t)N_TOT * D];   // ~185 MB node embedding store
__device__ double g_acc[8];
__device__ unsigned short g_lists[LVLS][MM];    // node ids bucketed by rule
__device__ int            g_offs[LVLS][N_RULES + 1];

// ---------------- init: axiom embeddings + zero accumulators ----------------
__global__ void init_kernel(const float* __restrict__ thax_table,
                            const float* __restrict__ sine_table,
                            const int*   __restrict__ init_thax,
                            const int*   __restrict__ init_sine)
{
    int idx = blockIdx.x * blockDim.x + threadIdx.x;
    if (blockIdx.x == 0 && threadIdx.x < 8) g_acc[threadIdx.x] = 0.0;
    int total = N_INIT * (D / 4);
    if (idx >= total) return;
    int n = idx >> 5;
    int q = idx & 31;
    const float4* ta = (const float4*)(thax_table + (size_t)init_thax[n] * D);
    const float4* sa = (const float4*)(sine_table + (size_t)init_sine[n] * D);
    float4 a = ta[q], b = sa[q], o;
    o.x = a.x + b.x; o.y = a.y + b.y; o.z = a.z + b.z; o.w = a.w + b.w;
    ((float4*)(g_store + (size_t)n * D))[q] = o;
}

// ---------------- bucket nodes by rule (once, all levels) ----------------
__global__ void bucket_kernel(const int* __restrict__ rules)
{
    __shared__ int hist[N_RULES];
    __shared__ int scan[N_RULES];
    __shared__ int cursor[N_RULES];
    const int lvl = blockIdx.x;
    const int t = threadIdx.x;     // 256 threads

    hist[t] = 0;
    __syncthreads();
    const int* lr = rules + lvl * MM;
    for (int m = t; m < MM; m += 256) atomicAdd(&hist[lr[m]], 1);
    __syncthreads();

    scan[t] = hist[t];
    __syncthreads();
    for (int off = 1; off < N_RULES; off <<= 1) {
        int add = (t >= off) ? scan[t - off] : 0;
        __syncthreads();
        scan[t] += add;
        __syncthreads();
    }
    // exclusive offsets
    int excl = scan[t] - hist[t];
    g_offs[lvl][t] = excl;
    cursor[t] = excl;
    if (t == 0) g_offs[lvl][N_RULES] = MM;
    __syncthreads();

    for (int m = t; m < MM; m += 256) {
        int r = lr[m];
        int p = atomicAdd(&cursor[r], 1);
        g_lists[lvl][p] = (unsigned short)m;
    }
}

// ---------------- tf32 mma helpers ----------------
__device__ __forceinline__ uint32_t f2tf32(float x) {
    uint32_t r;
    asm("cvt.rna.tf32.f32 %0, %1;" : "=r"(r) : "f"(x));
    return r;
}

__device__ __forceinline__ void mma_tf32(float c[4], const uint32_t a[4],
                                         uint32_t b0, uint32_t b1) {
    asm volatile(
        "mma.sync.aligned.m16n8k8.row.col.f32.tf32.tf32.f32 "
        "{%0,%1,%2,%3}, {%4,%5,%6,%7}, {%8,%9}, {%0,%1,%2,%3};"
        : "+f"(c[0]), "+f"(c[1]), "+f"(c[2]), "+f"(c[3])
        : "r"(a[0]), "r"(a[1]), "r"(a[2]), "r"(a[3]), "r"(b0), "r"(b1));
}

// ---------------- per-level rule-grouped MLP (tensor core) ----------------
// grid = N_RULES*2 (rule, col-half of 64), block = 128 threads (4 warps).
// warp w covers cols [half*64 + w*16, +16) = 2 n-tiles of 8.
// X (up to 32 nodes x 256 k) staged in smem; W streamed from global as
// mma B-fragments (8-consecutive-col groups -> full 32B sector efficiency).
__global__ __launch_bounds__(128, 4)
void level_kernel(int lvl,
                  const float* __restrict__ rule_W,
                  const float* __restrict__ rule_b,
                  const int*   __restrict__ parents)
{
    __shared__ float sX[32 * XSTRIDE];   // 33280 B

    const int rule = blockIdx.x >> 1;
    const int half = blockIdx.x & 1;
    const int t    = threadIdx.x;
    const int lane = t & 31;
    const int wid  = t >> 5;

    const int beg = g_offs[lvl][rule];
    const int count = g_offs[lvl][rule + 1] - beg;
    if (count == 0) return;

    const unsigned short* list = g_lists[lvl] + beg;
    const int* lp = parents + (size_t)lvl * MM * 2;
    const float* Wbase = rule_W + (size_t)rule * TWOD * D;
    const int ncolw = half * 64 + wid * 16;

    const int tg  = lane & 3;    // thread-in-group (k offset / col pair)
    const int grp = lane >> 2;   // group (row / col)

    for (int g0 = 0; g0 < count; g0 += 32) {
        // ---- stage X: 32 slots x 256 k, 4 threads per slot ----
        {
            int slot = t >> 2;
            int sub  = t & 3;                      // parent = sub>>1, half64 = sub&1
            int idx  = g0 + slot;
            float4* dst = (float4*)(sX + slot * XSTRIDE + (sub >> 1) * 128 + (sub & 1) * 64);
            if (idx < count) {
                int m = list[idx];
                int p = lp[2 * m + (sub >> 1)];
                const float4* src = (const float4*)(g_store + (size_t)p * D + (sub & 1) * 64);
                #pragma unroll
                for (int j = 0; j < 16; j++) dst[j] = src[j];
            } else {
                #pragma unroll
                for (int j = 0; j < 16; j++) dst[j] = make_float4(0.f, 0.f, 0.f, 0.f);
            }
        }
        __syncthreads();

        // ---- 32x32 tile of the (count x 128) GEMM via tf32 mma ----
        float c[2][2][4];
        #pragma unroll
        for (int mt = 0; mt < 2; mt++)
            #pragma unroll
            for (int nt = 0; nt < 2; nt++)
                #pragma unroll
                for (int j = 0; j < 4; j++) c[mt][nt][j] = 0.f;

        #pragma unroll 4
        for (int kt = 0; kt < 32; kt++) {
            const int kb = kt * 8;
            uint32_t a[2][4];
            #pragma unroll
            for (int mt = 0; mt < 2; mt++) {
                const float* xr = sX + (mt * 16 + grp) * XSTRIDE + kb + tg;
                a[mt][0] = f2tf32(xr[0]);
                a[mt][1] = f2tf32(xr[8 * XSTRIDE]);
                a[mt][2] = f2tf32(xr[4]);
                a[mt][3] = f2tf32(xr[8 * XSTRIDE + 4]);
            }
            #pragma unroll
            for (int nt = 0; nt < 2; nt++) {
                const float* wb = Wbase + (size_t)(kb + tg) * D + ncolw + nt * 8 + grp;
                uint32_t b0 = f2tf32(wb[0]);
                uint32_t b1 = f2tf32(wb[4 * D]);
                mma_tf32(c[0][nt], a[0], b0, b1);
                mma_tf32(c[1][nt], a[1], b0, b1);
            }
        }

        // ---- epilogue: bias + ReLU + scattered float2 stores ----
        float* outbase = g_store + (size_t)(N_INIT + lvl * MM) * D;
        #pragma unroll
        for (int nt = 0; nt < 2; nt++) {
            int col = ncolw + nt * 8 + 2 * tg;
            float2 bias = *(const float2*)(rule_b + (size_t)rule * D + col);
            #pragma unroll
            for (int mt = 0; mt < 2; mt++) {
                int r0 = g0 + mt * 16 + grp;
                if (r0 < count) {
                    int m = list[r0];
                    float2 o;
                    o.x = fmaxf(c[mt][nt][0] + bias.x, 0.f);
                    o.y = fmaxf(c[mt][nt][1] + bias.y, 0.f);
                    *(float2*)(outbase + (size_t)m * D + col) = o;
                }
                if (r0 + 8 < count) {
                    int m = list[r0 + 8];
                    float2 o;
                    o.x = fmaxf(c[mt][nt][2] + bias.x, 0.f);
                    o.y = fmaxf(c[mt][nt][3] + bias.y, 0.f);
                    *(float2*)(outbase + (size_t)m * D + col) = o;
                }
            }
        }
        __syncthreads();
    }
}

// ---------------- final reduction ----------------
__device__ __forceinline__ float softplusf(float x) {
    return fmaxf(x, 0.f) + log1pf(expf(-fabsf(x)));
}

__global__ void reduce_kernel(const float* __restrict__ eval_w,
                              const float* __restrict__ eval_b,
                              const float* __restrict__ pos_vals,
                              const float* __restrict__ neg_vals)
{
    __shared__ double part[6];
    const int lane = threadIdx.x & 31;
    const int wid  = threadIdx.x >> 5;
    const int warpsPerBlock = blockDim.x >> 5;
    const int gw  = blockIdx.x * warpsPerBlock + wid;
    const int nw  = gridDim.x * warpsPerBlock;

    const float4 ew = ((const float4*)eval_w)[lane];
    const float  eb = eval_b[0];

    double a = 0, b = 0, sp = 0, sn = 0, pok = 0, nok = 0;
    for (int row = gw; row < N_TOT; row += nw) {
        float4 v = ((const float4*)(g_store + (size_t)row * D))[lane];
        float s = v.x * ew.x + v.y * ew.y + v.z * ew.z + v.w * ew.w;
        #pragma unroll
        for (int o = 16; o; o >>= 1) s += __shfl_xor_sync(0xffffffffu, s, o);
        if (lane == 0) {
            float logit = s + eb;
            float pv = pos_vals[row], nv = neg_vals[row];
            a  += (double)(pv * softplusf(-logit));
            b  += (double)(nv * softplusf(logit));
            sp += (double)pv;
            sn += (double)nv;
            if (logit >= 0.f) pok += (double)pv; else nok += (double)nv;
        }
    }
    if (threadIdx.x < 6) part[threadIdx.x] = 0.0;
    __syncthreads();
    if (lane == 0) {
        atomicAdd(&part[0], a);  atomicAdd(&part[1], b);
        atomicAdd(&part[2], sp); atomicAdd(&part[3], sn);
        atomicAdd(&part[4], pok); atomicAdd(&part[5], nok);
    }
    __syncthreads();
    if (threadIdx.x < 6) atomicAdd(&g_acc[threadIdx.x], part[threadIdx.x]);
}

__global__ void finalize_kernel(float* out, int out_size)
{
    double A = g_acc[0], B = g_acc[1], P = g_acc[2], N = g_acc[3];
    double loss = (N / P) * A + B;
    if (out_size > 0) out[0] = (float)loss;
    if (out_size > 1) out[1] = (float)g_acc[4];
    if (out_size > 2) out[2] = (float)g_acc[5];
}

// ---------------- launch ----------------
extern "C" void kernel_launch(void* const* d_in, const int* in_sizes, int n_in,
                              void* d_out, int out_size)
{
    const float* thax_table = (const float*)d_in[0];
    const float* sine_table = (const float*)d_in[1];
    const float* rule_W     = (const float*)d_in[2];
    const float* rule_b     = (const float*)d_in[3];
    const float* eval_w     = (const float*)d_in[4];
    const float* eval_b     = (const float*)d_in[5];
    const float* pos_vals   = (const float*)d_in[6];
    const float* neg_vals   = (const float*)d_in[7];
    const int*   init_thax  = (const int*)d_in[8];
    const int*   init_sine  = (const int*)d_in[9];
    const int*   parents    = (const int*)d_in[10];
    const int*   rules      = (const int*)d_in[11];

    {   // axiom embeddings + accumulator reset
        int total = N_INIT * (D / 4);
        int blocks = (total + 255) / 256;
        init_kernel<<<blocks, 256>>>(thax_table, sine_table, init_thax, init_sine);
    }
    bucket_kernel<<<LVLS, N_RULES>>>(rules);

    for (int l = 0; l < LVLS; l++) {
        level_kernel<<<N_RULES * 2, 128>>>(l, rule_W, rule_b, parents);
    }

    reduce_kernel<<<1184, 256>>>(eval_w, eval_b, pos_vals, neg_vals);
    finalize_kernel<<<1, 1>>>((float*)d_out, out_size);
}

// round 3
// speedup vs baseline: 2.8962x; 1.4798x over previous
#include <cuda_runtime.h>
#include <cuda_bf16.h>
#include <cstdint>

#define D       128
#define TWOD    256
#define N_INIT  100000
#define LVLS    64
#define MM      4096
#define N_RULES 256
#define N_TOT   (N_INIT + LVLS * MM)

#define XS       264      // bf16 elements per sX row (256 + 8 pad -> 528B, LDSM conflict-free)
#define MAX_WORK 512      // sum ceil(count/16) <= 256 + 256

// ---------------- device scratch (no allocations allowed) ----------------
__device__ float  g_store[(size_t)N_TOT * D];            // ~185 MB embeddings
__device__ double g_acc[8];
__device__ unsigned short g_lists[LVLS][MM];             // node ids bucketed by rule
__device__ int            g_offs[LVLS][N_RULES + 1];
__device__ unsigned int   g_work[LVLS][MAX_WORK];        // (rule<<16)|groupStart
__device__ int            g_nwork[LVLS];
__device__ uint2          g_Wfrag[(size_t)N_RULES * 16 * 16 * 32];  // 16 MB bf16 B-fragments

// ---------------- helpers ----------------
__device__ __forceinline__ uint32_t packbf(float lo, float hi) {
    __nv_bfloat162 h = __float22bfloat162_rn(make_float2(lo, hi));
    return *reinterpret_cast<uint32_t*>(&h);
}

__device__ __forceinline__ void mma_bf16(float c[4], uint32_t a0, uint32_t a1,
                                         uint32_t a2, uint32_t a3, uint2 b) {
    asm volatile(
        "mma.sync.aligned.m16n8k16.row.col.f32.bf16.bf16.f32 "
        "{%0,%1,%2,%3}, {%4,%5,%6,%7}, {%8,%9}, {%0,%1,%2,%3};"
        : "+f"(c[0]), "+f"(c[1]), "+f"(c[2]), "+f"(c[3])
        : "r"(a0), "r"(a1), "r"(a2), "r"(a3), "r"(b.x), "r"(b.y));
}

// ---------------- init: axiom embeddings + zero accumulators ----------------
__global__ void init_kernel(const float* __restrict__ thax_table,
                            const float* __restrict__ sine_table,
                            const int*   __restrict__ init_thax,
                            const int*   __restrict__ init_sine)
{
    int idx = blockIdx.x * blockDim.x + threadIdx.x;
    if (blockIdx.x == 0 && threadIdx.x < 8) g_acc[threadIdx.x] = 0.0;
    int total = N_INIT * (D / 4);
    if (idx >= total) return;
    int n = idx >> 5;
    int q = idx & 31;
    const float4* ta = (const float4*)(thax_table + (size_t)init_thax[n] * D);
    const float4* sa = (const float4*)(sine_table + (size_t)init_sine[n] * D);
    float4 a = ta[q], b = sa[q], o;
    o.x = a.x + b.x; o.y = a.y + b.y; o.z = a.z + b.z; o.w = a.w + b.w;
    ((float4*)(g_store + (size_t)n * D))[q] = o;
}

// ---------------- one-time: pack W into mma B-fragment layout, bf16 ----------------
// frag index = ((rule*16 + kstep)*16 + ntile)*32 + lane
// lane holds b0 = {W[k0][n], W[k0+1][n]}, b1 = {W[k0+8][n], W[k0+9][n]}
// with k0 = kstep*16 + (lane&3)*2, n = ntile*8 + lane/4.
__global__ void pack_kernel(const float* __restrict__ rule_W)
{
    int rule  = blockIdx.x >> 4;
    int kstep = blockIdx.x & 15;
    int ntile = threadIdx.x >> 5;
    int lane  = threadIdx.x & 31;
    int k0 = kstep * 16 + (lane & 3) * 2;
    int n  = ntile * 8 + (lane >> 2);
    const float* base = rule_W + ((size_t)rule * TWOD + k0) * D + n;
    uint2 v;
    v.x = packbf(base[0],     base[D]);
    v.y = packbf(base[8 * D], base[9 * D]);
    g_Wfrag[(((size_t)rule * 16 + kstep) * 16 + ntile) * 32 + lane] = v;
}

// ---------------- bucket nodes by rule + emit work items (once) ----------------
__global__ void bucket_kernel(const int* __restrict__ rules)
{
    __shared__ int hist[N_RULES];
    __shared__ int scan[N_RULES];
    __shared__ int cursor[N_RULES];
    __shared__ int nw;
    const int lvl = blockIdx.x;
    const int t = threadIdx.x;     // 256 threads

    hist[t] = 0;
    if (t == 0) nw = 0;
    __syncthreads();
    const int* lr = rules + lvl * MM;
    for (int m = t; m < MM; m += 256) atomicAdd(&hist[lr[m]], 1);
    __syncthreads();

    scan[t] = hist[t];
    __syncthreads();
    for (int off = 1; off < N_RULES; off <<= 1) {
        int add = (t >= off) ? scan[t - off] : 0;
        __syncthreads();
        scan[t] += add;
        __syncthreads();
    }
    int excl = scan[t] - hist[t];
    g_offs[lvl][t] = excl;
    cursor[t] = excl;
    if (t == 0) g_offs[lvl][N_RULES] = MM;

    // emit 16-node work groups for this rule
    for (int g = 0; g < hist[t]; g += 16) {
        int p = atomicAdd(&nw, 1);
        g_work[lvl][p] = ((unsigned)t << 16) | (unsigned)g;
    }
    __syncthreads();
    if (t == 0) g_nwork[lvl] = nw;

    for (int m = t; m < MM; m += 256) {
        int r = lr[m];
        int p = atomicAdd(&cursor[r], 1);
        g_lists[lvl][p] = (unsigned short)m;
    }
}

// ---------------- per-level MLP: bf16 tensor-core ----------------
// grid = (MAX_WORK, 2): x = work item (rule, 16-node group), y = 64-col half.
// block = 128 (4 warps); warp w covers cols [half*64 + w*16, +16) (2 n-tiles).
__global__ __launch_bounds__(128)
void level_kernel(int lvl,
                  const float* __restrict__ rule_b,
                  const int*   __restrict__ parents)
{
    __shared__ __nv_bfloat16 sX[16 * XS];   // 8448 B
    __shared__ int sM[16];

    const int wi = blockIdx.x;
    if (wi >= g_nwork[lvl]) return;
    const unsigned w = g_work[lvl][wi];
    const int rule   = (int)(w >> 16);
    const int gstart = (int)(w & 0xffff);
    const int beg    = g_offs[lvl][rule] + gstart;
    const int nodes  = min(16, g_offs[lvl][rule + 1] - beg);

    const unsigned short* list = g_lists[lvl] + beg;
    const int* lp = parents + (size_t)lvl * MM * 2;
    const int t = threadIdx.x, lane = t & 31, wid = t >> 5;
    const int half = blockIdx.y;

    if (t < 16) sM[t] = (t < nodes) ? (int)list[t] : 0;

    // ---- stage X: 16 nodes x 256 k, fp32 gather -> bf16 smem ----
    {
        int slot = t >> 3, sub = t & 7;
        int par = sub >> 2, off = (sub & 3) * 32;     // 32 floats per thread
        uint32_t tmp[16];
        if (slot < nodes) {
            int m = list[slot];
            int p = lp[2 * m + par];
            const float4* src = (const float4*)(g_store + (size_t)p * D + off);
            #pragma unroll
            for (int j = 0; j < 8; j++) {
                float4 v = src[j];
                tmp[2 * j]     = packbf(v.x, v.y);
                tmp[2 * j + 1] = packbf(v.z, v.w);
            }
        } else {
            #pragma unroll
            for (int j = 0; j < 16; j++) tmp[j] = 0u;
        }
        uint4* dst = (uint4*)(sX + slot * XS + par * 128 + off);
        #pragma unroll
        for (int j = 0; j < 4; j++)
            dst[j] = make_uint4(tmp[4 * j], tmp[4 * j + 1], tmp[4 * j + 2], tmp[4 * j + 3]);
    }
    __syncthreads();

    // ---- 16x32 warp tile: 16 k-steps of m16n8k16 ----
    const int nt0 = half * 8 + wid * 2;
    const uint2* fb = g_Wfrag + (size_t)rule * (16 * 16 * 32) + nt0 * 32 + lane;
    float c0[4] = {0.f, 0.f, 0.f, 0.f};
    float c1[4] = {0.f, 0.f, 0.f, 0.f};
    const uint32_t arow = (uint32_t)__cvta_generic_to_shared(
        sX + (lane & 15) * XS + (lane >> 4) * 8);

    #pragma unroll 4
    for (int kt = 0; kt < 16; kt++) {
        uint32_t a0, a1, a2, a3;
        asm volatile(
            "ldmatrix.sync.aligned.m8n8.x4.shared.b16 {%0,%1,%2,%3}, [%4];"
            : "=r"(a0), "=r"(a1), "=r"(a2), "=r"(a3)
            : "r"(arow + kt * 32));
        uint2 b0 = fb[kt * 512];
        uint2 b1 = fb[kt * 512 + 32];
        mma_bf16(c0, a0, a1, a2, a3, b0);
        mma_bf16(c1, a0, a1, a2, a3, b1);
    }

    // ---- epilogue: bias + ReLU + float2 scattered stores ----
    const float* bias = rule_b + (size_t)rule * D;
    float* outb = g_store + (size_t)(N_INIT + lvl * MM) * D;
    const int r0 = lane >> 2;
    #pragma unroll
    for (int nt = 0; nt < 2; nt++) {
        const float* cc = nt ? c1 : c0;
        int col = (nt0 + nt) * 8 + 2 * (lane & 3);
        float2 bs = *(const float2*)(bias + col);
        if (r0 < nodes) {
            int m = sM[r0];
            float2 o;
            o.x = fmaxf(cc[0] + bs.x, 0.f);
            o.y = fmaxf(cc[1] + bs.y, 0.f);
            *(float2*)(outb + (size_t)m * D + col) = o;
        }
        if (r0 + 8 < nodes) {
            int m = sM[r0 + 8];
            float2 o;
            o.x = fmaxf(cc[2] + bs.x, 0.f);
            o.y = fmaxf(cc[3] + bs.y, 0.f);
            *(float2*)(outb + (size_t)m * D + col) = o;
        }
    }
}

// ---------------- final reduction ----------------
__device__ __forceinline__ float softplusf(float x) {
    return fmaxf(x, 0.f) + log1pf(expf(-fabsf(x)));
}

__global__ void reduce_kernel(const float* __restrict__ eval_w,
                              const float* __restrict__ eval_b,
                              const float* __restrict__ pos_vals,
                              const float* __restrict__ neg_vals)
{
    __shared__ double part[6];
    const int lane = threadIdx.x & 31;
    const int wid  = threadIdx.x >> 5;
    const int warpsPerBlock = blockDim.x >> 5;
    const int gw  = blockIdx.x * warpsPerBlock + wid;
    const int nw  = gridDim.x * warpsPerBlock;

    const float4 ew = ((const float4*)eval_w)[lane];
    const float  eb = eval_b[0];

    double a = 0, b = 0, sp = 0, sn = 0, pok = 0, nok = 0;
    for (int row = gw; row < N_TOT; row += nw) {
        float4 v = ((const float4*)(g_store + (size_t)row * D))[lane];
        float s = v.x * ew.x + v.y * ew.y + v.z * ew.z + v.w * ew.w;
        #pragma unroll
        for (int o = 16; o; o >>= 1) s += __shfl_xor_sync(0xffffffffu, s, o);
        if (lane == 0) {
            float logit = s + eb;
            float pv = pos_vals[row], nv = neg_vals[row];
            a  += (double)(pv * softplusf(-logit));
            b  += (double)(nv * softplusf(logit));
            sp += (double)pv;
            sn += (double)nv;
            if (logit >= 0.f) pok += (double)pv; else nok += (double)nv;
        }
    }
    if (threadIdx.x < 6) part[threadIdx.x] = 0.0;
    __syncthreads();
    if (lane == 0) {
        atomicAdd(&part[0], a);  atomicAdd(&part[1], b);
        atomicAdd(&part[2], sp); atomicAdd(&part[3], sn);
        atomicAdd(&part[4], pok); atomicAdd(&part[5], nok);
    }
    __syncthreads();
    if (threadIdx.x < 6) atomicAdd(&g_acc[threadIdx.x], part[threadIdx.x]);
}

__global__ void finalize_kernel(float* out, int out_size)
{
    double A = g_acc[0], B = g_acc[1], P = g_acc[2], N = g_acc[3];
    double loss = (N / P) * A + B;
    if (out_size > 0) out[0] = (float)loss;
    if (out_size > 1) out[1] = (float)g_acc[4];
    if (out_size > 2) out[2] = (float)g_acc[5];
}

// ---------------- launch ----------------
extern "C" void kernel_launch(void* const* d_in, const int* in_sizes, int n_in,
                              void* d_out, int out_size)
{
    const float* thax_table = (const float*)d_in[0];
    const float* sine_table = (const float*)d_in[1];
    const float* rule_W     = (const float*)d_in[2];
    const float* rule_b     = (const float*)d_in[3];
    const float* eval_w     = (const float*)d_in[4];
    const float* eval_b     = (const float*)d_in[5];
    const float* pos_vals   = (const float*)d_in[6];
    const float* neg_vals   = (const float*)d_in[7];
    const int*   init_thax  = (const int*)d_in[8];
    const int*   init_sine  = (const int*)d_in[9];
    const int*   parents    = (const int*)d_in[10];
    const int*   rules      = (const int*)d_in[11];

    {   // axiom embeddings + accumulator reset
        int total = N_INIT * (D / 4);
        int blocks = (total + 255) / 256;
        init_kernel<<<blocks, 256>>>(thax_table, sine_table, init_thax, init_sine);
    }
    pack_kernel<<<N_RULES * 16, 512>>>(rule_W);
    bucket_kernel<<<LVLS, N_RULES>>>(rules);

    dim3 lgrid(MAX_WORK, 2);
    for (int l = 0; l < LVLS; l++) {
        level_kernel<<<lgrid, 128>>>(l, rule_b, parents);
    }

    reduce_kernel<<<1184, 256>>>(eval_w, eval_b, pos_vals, neg_vals);
    finalize_kernel<<<1, 1>>>((float*)d_out, out_size);
}

// round 4
// speedup vs baseline: 3.0291x; 1.0459x over previous
#include <cuda_runtime.h>
#include <cuda_bf16.h>
#include <cstdint>

#define D       128
#define TWOD    256
#define N_INIT  100000
#define LVLS    64
#define MM      4096
#define N_RULES 256
#define N_TOT   (N_INIT + LVLS * MM)

#define XS    264      // bf16 per sX row (256 + 8 pad -> 528B, ldmatrix conflict-free)
#define NCTA  256      // persistent grid: one CTA per rule
#define WSMEM 65536    // 64 KB of packed W fragments per rule

// ---------------- device scratch (no allocations allowed) ----------------
__device__ float  g_store[(size_t)N_TOT * D];            // ~185 MB embeddings
__device__ double g_acc[8];
__device__ unsigned short g_lists[LVLS][MM];             // node ids bucketed by rule
__device__ int            g_offs[LVLS][N_RULES + 1];
__device__ uint2          g_Wfrag[(size_t)N_RULES * 16 * 16 * 32];  // 16 MB bf16 B-frags
__device__ int            g_bar_arrive;
__device__ volatile int   g_bar_release;

// ---------------- helpers ----------------
__device__ __forceinline__ uint32_t packbf(float lo, float hi) {
    __nv_bfloat162 h = __float22bfloat162_rn(make_float2(lo, hi));
    return *reinterpret_cast<uint32_t*>(&h);
}

__device__ __forceinline__ void mma_bf16(float c[4], uint32_t a0, uint32_t a1,
                                         uint32_t a2, uint32_t a3, uint2 b) {
    asm volatile(
        "mma.sync.aligned.m16n8k16.row.col.f32.bf16.bf16.f32 "
        "{%0,%1,%2,%3}, {%4,%5,%6,%7}, {%8,%9}, {%0,%1,%2,%3};"
        : "+f"(c[0]), "+f"(c[1]), "+f"(c[2]), "+f"(c[3])
        : "r"(a0), "r"(a1), "r"(a2), "r"(a3), "r"(b.x), "r"(b.y));
}

// ---------------- init: axiom embeddings + zero accumulators/barrier ----------------
__global__ void init_kernel(const float* __restrict__ thax_table,
                            const float* __restrict__ sine_table,
                            const int*   __restrict__ init_thax,
                            const int*   __restrict__ init_sine)
{
    int idx = blockIdx.x * blockDim.x + threadIdx.x;
    if (blockIdx.x == 0 && threadIdx.x < 8) g_acc[threadIdx.x] = 0.0;
    if (blockIdx.x == 0 && threadIdx.x == 0) { g_bar_arrive = 0; g_bar_release = 0; }
    int total = N_INIT * (D / 4);
    if (idx >= total) return;
    int n = idx >> 5;
    int q = idx & 31;
    const float4* ta = (const float4*)(thax_table + (size_t)init_thax[n] * D);
    const float4* sa = (const float4*)(sine_table + (size_t)init_sine[n] * D);
    float4 a = ta[q], b = sa[q], o;
    o.x = a.x + b.x; o.y = a.y + b.y; o.z = a.z + b.z; o.w = a.w + b.w;
    ((float4*)(g_store + (size_t)n * D))[q] = o;
}

// ---------------- one-time: pack W into mma B-fragment layout, bf16 ----------------
// frag index = ((rule*16 + kstep)*16 + ntile)*32 + lane
// lane: b0 = {W[k0][n], W[k0+1][n]}, b1 = {W[k0+8][n], W[k0+9][n]}
// k0 = kstep*16 + (lane&3)*2, n = ntile*8 + lane/4.
__global__ void pack_kernel(const float* __restrict__ rule_W)
{
    int rule  = blockIdx.x >> 4;
    int kstep = blockIdx.x & 15;
    int ntile = threadIdx.x >> 5;
    int lane  = threadIdx.x & 31;
    int k0 = kstep * 16 + (lane & 3) * 2;
    int n  = ntile * 8 + (lane >> 2);
    const float* base = rule_W + ((size_t)rule * TWOD + k0) * D + n;
    uint2 v;
    v.x = packbf(base[0],     base[D]);
    v.y = packbf(base[8 * D], base[9 * D]);
    g_Wfrag[(((size_t)rule * 16 + kstep) * 16 + ntile) * 32 + lane] = v;
}

// ---------------- bucket nodes by rule (once, all levels) ----------------
__global__ void bucket_kernel(const int* __restrict__ rules)
{
    __shared__ int hist[N_RULES];
    __shared__ int scan[N_RULES];
    __shared__ int cursor[N_RULES];
    const int lvl = blockIdx.x;
    const int t = threadIdx.x;     // 256 threads

    hist[t] = 0;
    __syncthreads();
    const int* lr = rules + lvl * MM;
    for (int m = t; m < MM; m += 256) atomicAdd(&hist[lr[m]], 1);
    __syncthreads();

    scan[t] = hist[t];
    __syncthreads();
    for (int off = 1; off < N_RULES; off <<= 1) {
        int add = (t >= off) ? scan[t - off] : 0;
        __syncthreads();
        scan[t] += add;
        __syncthreads();
    }
    int excl = scan[t] - hist[t];
    g_offs[lvl][t] = excl;
    cursor[t] = excl;
    if (t == 0) g_offs[lvl][N_RULES] = MM;
    __syncthreads();

    for (int m = t; m < MM; m += 256) {
        int r = lr[m];
        int p = atomicAdd(&cursor[r], 1);
        g_lists[lvl][p] = (unsigned short)m;
    }
}

// ---------------- persistent all-levels MLP ----------------
// grid = 256 CTAs (one rule each), block = 256 threads (8 warps).
// Rule's W fragments live in smem for the whole kernel. Device-wide barrier
// between levels (monotonic arrive counter + volatile release flag).
__global__ __launch_bounds__(256)
void level_persistent(const float* __restrict__ rule_b,
                      const int*   __restrict__ parents)
{
    extern __shared__ uint2 sW[];                 // [16*16*32] = 64 KB
    __shared__ __nv_bfloat16 sX[16 * XS];         // 8448 B
    __shared__ int sM[16];

    const int rule = blockIdx.x;
    const int t = threadIdx.x, lane = t & 31, wid = t >> 5;

    // ---- stage this rule's W fragments once ----
    {
        const uint4* src = (const uint4*)(g_Wfrag + (size_t)rule * (16 * 16 * 32));
        uint4* dst = (uint4*)sW;
        #pragma unroll 4
        for (int i = t; i < WSMEM / 16; i += 256) dst[i] = src[i];
    }

    // per-warp constants
    const int nt0 = wid * 2;                      // warp covers ntiles {nt0, nt0+1}
    const int col0 = nt0 * 8 + 2 * (lane & 3);
    const int col1 = col0 + 8;
    const float2 bs0 = *(const float2*)(rule_b + (size_t)rule * D + col0);
    const float2 bs1 = *(const float2*)(rule_b + (size_t)rule * D + col1);
    const int r0 = lane >> 2;
    const uint32_t arow = (uint32_t)__cvta_generic_to_shared(
        sX + (lane & 15) * XS + (lane >> 4) * 8);

    for (int lvl = 0; lvl < LVLS; lvl++) {
        const int beg   = g_offs[lvl][rule];
        const int count = g_offs[lvl][rule + 1] - beg;
        const unsigned short* list = g_lists[lvl] + beg;
        const int* lp = parents + (size_t)lvl * MM * 2;
        float* outb = g_store + (size_t)(N_INIT + lvl * MM) * D;

        for (int g0 = 0; g0 < count; g0 += 16) {
            const int nodes = min(16, count - g0);

            if (t < 16) sM[t] = (t < nodes) ? (int)list[g0 + t] : 0;

            // ---- stage X: 16 nodes x 256 k, __ldcg fp32 gather -> bf16 smem ----
            {
                int slot = t >> 4, sub = t & 15;
                int par = sub >> 3, seg = sub & 7;        // 16 floats per thread
                uint32_t tmp[8];
                if (slot < nodes) {
                    int m = list[g0 + slot];
                    int p = lp[2 * m + par];
                    const float4* src = (const float4*)(g_store + (size_t)p * D + seg * 16);
                    #pragma unroll
                    for (int j = 0; j < 4; j++) {
                        float4 v = __ldcg(src + j);
                        tmp[2 * j]     = packbf(v.x, v.y);
                        tmp[2 * j + 1] = packbf(v.z, v.w);
                    }
                } else {
                    #pragma unroll
                    for (int j = 0; j < 8; j++) tmp[j] = 0u;
                }
                uint4* dst = (uint4*)(sX + slot * XS + par * 128 + seg * 16);
                dst[0] = make_uint4(tmp[0], tmp[1], tmp[2], tmp[3]);
                dst[1] = make_uint4(tmp[4], tmp[5], tmp[6], tmp[7]);
            }
            __syncthreads();

            // ---- 16x16 cols per warp: 16 k-steps of m16n8k16 ----
            float c0[4] = {0.f, 0.f, 0.f, 0.f};
            float c1[4] = {0.f, 0.f, 0.f, 0.f};
            #pragma unroll 4
            for (int kt = 0; kt < 16; kt++) {
                uint32_t a0, a1, a2, a3;
                asm volatile(
                    "ldmatrix.sync.aligned.m8n8.x4.shared.b16 {%0,%1,%2,%3}, [%4];"
                    : "=r"(a0), "=r"(a1), "=r"(a2), "=r"(a3)
                    : "r"(arow + kt * 32));
                uint2 b0 = sW[kt * 512 + nt0 * 32 + lane];
                uint2 b1 = sW[kt * 512 + (nt0 + 1) * 32 + lane];
                mma_bf16(c0, a0, a1, a2, a3, b0);
                mma_bf16(c1, a0, a1, a2, a3, b1);
            }

            // ---- epilogue: bias + ReLU + float2 scattered stores ----
            if (r0 < nodes) {
                int m = sM[r0];
                float2 o0, o1;
                o0.x = fmaxf(c0[0] + bs0.x, 0.f);
                o0.y = fmaxf(c0[1] + bs0.y, 0.f);
                o1.x = fmaxf(c1[0] + bs1.x, 0.f);
                o1.y = fmaxf(c1[1] + bs1.y, 0.f);
                *(float2*)(outb + (size_t)m * D + col0) = o0;
                *(float2*)(outb + (size_t)m * D + col1) = o1;
            }
            if (r0 + 8 < nodes) {
                int m = sM[r0 + 8];
                float2 o0, o1;
                o0.x = fmaxf(c0[2] + bs0.x, 0.f);
                o0.y = fmaxf(c0[3] + bs0.y, 0.f);
                o1.x = fmaxf(c1[2] + bs1.x, 0.f);
                o1.y = fmaxf(c1[3] + bs1.y, 0.f);
                *(float2*)(outb + (size_t)m * D + col0) = o0;
                *(float2*)(outb + (size_t)m * D + col1) = o1;
            }
            __syncthreads();   // protect sX/sM before next chunk
        }

        // ---- device-wide barrier before next level ----
        if (lvl < LVLS - 1) {
            __threadfence();
            __syncthreads();
            if (t == 0) {
                int v = atomicAdd(&g_bar_arrive, 1);
                if (v == NCTA * (lvl + 1) - 1) {
                    g_bar_release = lvl + 1;      // volatile store, L2-visible
                }
                while (g_bar_release < lvl + 1) __nanosleep(64);
            }
            __syncthreads();
        }
    }
}

// ---------------- final reduction ----------------
__device__ __forceinline__ float softplusf(float x) {
    return fmaxf(x, 0.f) + log1pf(expf(-fabsf(x)));
}

__global__ void reduce_kernel(const float* __restrict__ eval_w,
                              const float* __restrict__ eval_b,
                              const float* __restrict__ pos_vals,
                              const float* __restrict__ neg_vals)
{
    __shared__ double part[6];
    const int lane = threadIdx.x & 31;
    const int wid  = threadIdx.x >> 5;
    const int warpsPerBlock = blockDim.x >> 5;
    const int gw  = blockIdx.x * warpsPerBlock + wid;
    const int nw  = gridDim.x * warpsPerBlock;

    const float4 ew = ((const float4*)eval_w)[lane];
    const float  eb = eval_b[0];

    double a = 0, b = 0, sp = 0, sn = 0, pok = 0, nok = 0;
    for (int row = gw; row < N_TOT; row += nw) {
        float4 v = ((const float4*)(g_store + (size_t)row * D))[lane];
        float s = v.x * ew.x + v.y * ew.y + v.z * ew.z + v.w * ew.w;
        #pragma unroll
        for (int o = 16; o; o >>= 1) s += __shfl_xor_sync(0xffffffffu, s, o);
        if (lane == 0) {
            float logit = s + eb;
            float pv = pos_vals[row], nv = neg_vals[row];
            a  += (double)(pv * softplusf(-logit));
            b  += (double)(nv * softplusf(logit));
            sp += (double)pv;
            sn += (double)nv;
            if (logit >= 0.f) pok += (double)pv; else nok += (double)nv;
        }
    }
    if (threadIdx.x < 6) part[threadIdx.x] = 0.0;
    __syncthreads();
    if (lane == 0) {
        atomicAdd(&part[0], a);  atomicAdd(&part[1], b);
        atomicAdd(&part[2], sp); atomicAdd(&part[3], sn);
        atomicAdd(&part[4], pok); atomicAdd(&part[5], nok);
    }
    __syncthreads();
    if (threadIdx.x < 6) atomicAdd(&g_acc[threadIdx.x], part[threadIdx.x]);
}

__global__ void finalize_kernel(float* out, int out_size)
{
    double A = g_acc[0], B = g_acc[1], P = g_acc[2], N = g_acc[3];
    double loss = (N / P) * A + B;
    if (out_size > 0) out[0] = (float)loss;
    if (out_size > 1) out[1] = (float)g_acc[4];
    if (out_size > 2) out[2] = (float)g_acc[5];
}

// ---------------- launch ----------------
extern "C" void kernel_launch(void* const* d_in, const int* in_sizes, int n_in,
                              void* d_out, int out_size)
{
    const float* thax_table = (const float*)d_in[0];
    const float* sine_table = (const float*)d_in[1];
    const float* rule_W     = (const float*)d_in[2];
    const float* rule_b     = (const float*)d_in[3];
    const float* eval_w     = (const float*)d_in[4];
    const float* eval_b     = (const float*)d_in[5];
    const float* pos_vals   = (const float*)d_in[6];
    const float* neg_vals   = (const float*)d_in[7];
    const int*   init_thax  = (const int*)d_in[8];
    const int*   init_sine  = (const int*)d_in[9];
    const int*   parents    = (const int*)d_in[10];
    const int*   rules      = (const int*)d_in[11];

    cudaFuncSetAttribute(level_persistent,
                         cudaFuncAttributeMaxDynamicSharedMemorySize, WSMEM);

    {   // axiom embeddings + accumulator/barrier reset
        int total = N_INIT * (D / 4);
        int blocks = (total + 255) / 256;
        init_kernel<<<blocks, 256>>>(thax_table, sine_table, init_thax, init_sine);
    }
    pack_kernel<<<N_RULES * 16, 512>>>(rule_W);
    bucket_kernel<<<LVLS, N_RULES>>>(rules);

    level_persistent<<<NCTA, 256, WSMEM>>>(rule_b, parents);

    reduce_kernel<<<1184, 256>>>(eval_w, eval_b, pos_vals, neg_vals);
    finalize_kernel<<<1, 1>>>((float*)d_out, out_size);
}

// round 5
// speedup vs baseline: 4.6860x; 1.5470x over previous
#include <cuda_runtime.h>
#include <cuda_bf16.h>
#include <cstdint>

#define D       128
#define TWOD    256
#define N_INIT  100000
#define LVLS    64
#define MM      4096
#define N_RULES 256
#define N_TOT   (N_INIT + LVLS * MM)

#define XS    264      // bf16 per sX row (256 + 8 pad, ldmatrix conflict-free)
#define NCTA  256      // persistent grid: one CTA per rule (all co-resident)
#define WSMEM 65536    // 64 KB packed W fragments per rule

// ---------------- device scratch (no allocations allowed) ----------------
__device__ float  g_store[(size_t)N_TOT * D];            // ~185 MB embeddings
__device__ double g_acc[8];
__device__ unsigned short g_lists[LVLS][MM];             // node ids bucketed by rule
__device__ int            g_offs[LVLS][N_RULES + 1];
__device__ int            g_maxlvl[LVLS][N_RULES];       // max parent level (-1 none)
__device__ uint2          g_Wfrag[(size_t)N_RULES * 16 * 16 * 32];  // 16 MB B-frags
__device__ int            g_done[LVLS];                  // CTAs finished per level

// ---------------- helpers ----------------
__device__ __forceinline__ uint32_t packbf(float lo, float hi) {
    __nv_bfloat162 h = __float22bfloat162_rn(make_float2(lo, hi));
    return *reinterpret_cast<uint32_t*>(&h);
}

__device__ __forceinline__ void mma_bf16(float c[4], uint32_t a0, uint32_t a1,
                                         uint32_t a2, uint32_t a3, uint2 b) {
    asm volatile(
        "mma.sync.aligned.m16n8k16.row.col.f32.bf16.bf16.f32 "
        "{%0,%1,%2,%3}, {%4,%5,%6,%7}, {%8,%9}, {%0,%1,%2,%3};"
        : "+f"(c[0]), "+f"(c[1]), "+f"(c[2]), "+f"(c[3])
        : "r"(a0), "r"(a1), "r"(a2), "r"(a3), "r"(b.x), "r"(b.y));
}

// ---------------- init: axiom embeddings + zero counters ----------------
__global__ void init_kernel(const float* __restrict__ thax_table,
                            const float* __restrict__ sine_table,
                            const int*   __restrict__ init_thax,
                            const int*   __restrict__ init_sine)
{
    int idx = blockIdx.x * blockDim.x + threadIdx.x;
    if (blockIdx.x == 0 && threadIdx.x < 8)  g_acc[threadIdx.x] = 0.0;
    if (blockIdx.x == 0 && threadIdx.x < LVLS) g_done[threadIdx.x] = 0;
    int total = N_INIT * (D / 4);
    if (idx >= total) return;
    int n = idx >> 5;
    int q = idx & 31;
    const float4* ta = (const float4*)(thax_table + (size_t)init_thax[n] * D);
    const float4* sa = (const float4*)(sine_table + (size_t)init_sine[n] * D);
    float4 a = ta[q], b = sa[q], o;
    o.x = a.x + b.x; o.y = a.y + b.y; o.z = a.z + b.z; o.w = a.w + b.w;
    ((float4*)(g_store + (size_t)n * D))[q] = o;
}

// ---------------- one-time: pack W into mma B-fragment layout, bf16 ----------------
__global__ void pack_kernel(const float* __restrict__ rule_W)
{
    int rule  = blockIdx.x >> 4;
    int kstep = blockIdx.x & 15;
    int ntile = threadIdx.x >> 5;
    int lane  = threadIdx.x & 31;
    int k0 = kstep * 16 + (lane & 3) * 2;
    int n  = ntile * 8 + (lane >> 2);
    const float* base = rule_W + ((size_t)rule * TWOD + k0) * D + n;
    uint2 v;
    v.x = packbf(base[0],     base[D]);
    v.y = packbf(base[8 * D], base[9 * D]);
    g_Wfrag[(((size_t)rule * 16 + kstep) * 16 + ntile) * 32 + lane] = v;
}

// ---------------- bucket nodes by rule + max parent level (once) ----------------
__global__ void bucket_kernel(const int* __restrict__ rules,
                              const int* __restrict__ parents)
{
    __shared__ int hist[N_RULES];
    __shared__ int scan[N_RULES];
    __shared__ int cursor[N_RULES];
    __shared__ int maxp[N_RULES];
    const int lvl = blockIdx.x;
    const int t = threadIdx.x;     // 256 threads

    hist[t] = 0;
    maxp[t] = -1;
    __syncthreads();
    const int* lr = rules + lvl * MM;
    const int* lp = parents + (size_t)lvl * MM * 2;
    for (int m = t; m < MM; m += 256) {
        int r = lr[m];
        atomicAdd(&hist[r], 1);
        atomicMax(&maxp[r], max(lp[2 * m], lp[2 * m + 1]));
    }
    __syncthreads();

    scan[t] = hist[t];
    __syncthreads();
    for (int off = 1; off < N_RULES; off <<= 1) {
        int add = (t >= off) ? scan[t - off] : 0;
        __syncthreads();
        scan[t] += add;
        __syncthreads();
    }
    int excl = scan[t] - hist[t];
    g_offs[lvl][t] = excl;
    cursor[t] = excl;
    if (t == 0) g_offs[lvl][N_RULES] = MM;
    g_maxlvl[lvl][t] = (maxp[t] >= N_INIT) ? (maxp[t] - N_INIT) / MM : -1;
    __syncthreads();

    for (int m = t; m < MM; m += 256) {
        int r = lr[m];
        int p = atomicAdd(&cursor[r], 1);
        g_lists[lvl][p] = (unsigned short)m;
    }
}

// ---------------- persistent all-levels MLP, dataflow sync ----------------
// grid = 256 CTAs (one rule each), block = 256 (8 warps).
// Warp half h processes 16-node group g0+16h with 4 ntiles (32 cols) per warp.
// Cross-level sync: per-level done counters; CTA waits only for the max
// parent level it actually references.
__global__ __launch_bounds__(256)
void level_persistent(const float* __restrict__ rule_b,
                      const int*   __restrict__ parents)
{
    extern __shared__ uint2 sW[];                    // 64 KB
    __shared__ __nv_bfloat16 sX[2][16 * XS];         // 16.9 KB
    __shared__ int sM[2][16];

    const int rule = blockIdx.x;
    const int t = threadIdx.x, lane = t & 31, wid = t >> 5;

    // stage this rule's W fragments once
    {
        const uint4* src = (const uint4*)(g_Wfrag + (size_t)rule * (16 * 16 * 32));
        uint4* dst = (uint4*)sW;
        #pragma unroll 4
        for (int i = t; i < WSMEM / 16; i += 256) dst[i] = src[i];
    }

    const int wh  = wid >> 2;        // warp half (group)
    const int wl  = wid & 3;         // warp-in-half
    const int nt0 = wl * 4;          // 4 ntiles -> 32 cols
    const int r0  = lane >> 2;
    float2 bs[4];
    int cols[4];
    #pragma unroll
    for (int j = 0; j < 4; j++) {
        cols[j] = (nt0 + j) * 8 + 2 * (lane & 3);
        bs[j] = *(const float2*)(rule_b + (size_t)rule * D + cols[j]);
    }
    const uint32_t arow = (uint32_t)__cvta_generic_to_shared(
        &sX[wh][(lane & 15) * XS + (lane >> 4) * 8]);

    for (int lvl = 0; lvl < LVLS; lvl++) {
        const int beg   = g_offs[lvl][rule];
        const int count = g_offs[lvl][rule + 1] - beg;
        const unsigned short* list = g_lists[lvl] + beg;
        const int* lp = parents + (size_t)lvl * MM * 2;
        float* outb = g_store + (size_t)(N_INIT + lvl * MM) * D;

        // wait for the deepest parent level this (lvl, rule) references
        const int need = g_maxlvl[lvl][rule];
        if (need >= 0) {
            if (t == 0) {
                while (((volatile int*)g_done)[need] < NCTA) __nanosleep(32);
            }
            __syncthreads();
            __threadfence();
        }

        for (int g0 = 0; g0 < count; g0 += 32) {
            const int myg0   = g0 + wh * 16;
            const int nodesA = max(0, min(16, count - g0));
            const int nodesB = max(0, min(16, count - g0 - 16));
            const int nodes_h = wh ? nodesB : nodesA;

            if (t < 32) {
                int hh = t >> 4, sl = t & 15;
                int idx = g0 + hh * 16 + sl;
                sM[hh][sl] = (idx < count) ? (int)list[idx] : 0;
            }

            // ---- stage X (each half stages its own group) ----
            {
                int hh = t >> 7, tt = t & 127;
                int slot = tt >> 3, sub = tt & 7;
                int par = sub >> 2, seg = sub & 3;       // 32 floats per thread
                int idx = g0 + hh * 16 + slot;
                uint32_t tmp[16];
                if (idx < count) {
                    int m = list[idx];
                    int p = lp[2 * m + par];
                    const float4* src = (const float4*)(g_store + (size_t)p * D + seg * 32);
                    #pragma unroll
                    for (int j = 0; j < 8; j++) {
                        float4 v = __ldcg(src + j);
                        tmp[2 * j]     = packbf(v.x, v.y);
                        tmp[2 * j + 1] = packbf(v.z, v.w);
                    }
                } else {
                    #pragma unroll
                    for (int j = 0; j < 16; j++) tmp[j] = 0u;
                }
                uint4* dst = (uint4*)(&sX[hh][slot * XS + par * 128 + seg * 32]);
                #pragma unroll
                for (int j = 0; j < 4; j++)
                    dst[j] = make_uint4(tmp[4*j], tmp[4*j+1], tmp[4*j+2], tmp[4*j+3]);
            }
            __syncthreads();

            // ---- warp: 16 k-steps of m16n8k16 over 4 ntiles ----
            float c[4][4];
            #pragma unroll
            for (int j = 0; j < 4; j++)
                #pragma unroll
                for (int q = 0; q < 4; q++) c[j][q] = 0.f;

            #pragma unroll 4
            for (int kt = 0; kt < 16; kt++) {
                uint32_t a0, a1, a2, a3;
                asm volatile(
                    "ldmatrix.sync.aligned.m8n8.x4.shared.b16 {%0,%1,%2,%3}, [%4];"
                    : "=r"(a0), "=r"(a1), "=r"(a2), "=r"(a3)
                    : "r"(arow + kt * 32));
                #pragma unroll
                for (int j = 0; j < 4; j++) {
                    uint2 b = sW[kt * 512 + (nt0 + j) * 32 + lane];
                    mma_bf16(c[j], a0, a1, a2, a3, b);
                }
            }

            // ---- epilogue: bias + ReLU + float2 scattered stores ----
            if (r0 < nodes_h) {
                int m = sM[wh][r0];
                float* row = outb + (size_t)m * D;
                #pragma unroll
                for (int j = 0; j < 4; j++) {
                    float2 o;
                    o.x = fmaxf(c[j][0] + bs[j].x, 0.f);
                    o.y = fmaxf(c[j][1] + bs[j].y, 0.f);
                    *(float2*)(row + cols[j]) = o;
                }
            }
            if (r0 + 8 < nodes_h) {
                int m = sM[wh][r0 + 8];
                float* row = outb + (size_t)m * D;
                #pragma unroll
                for (int j = 0; j < 4; j++) {
                    float2 o;
                    o.x = fmaxf(c[j][2] + bs[j].x, 0.f);
                    o.y = fmaxf(c[j][3] + bs[j].y, 0.f);
                    *(float2*)(row + cols[j]) = o;
                }
            }
            __syncthreads();
        }

        // publish completion of this level
        __threadfence();
        __syncthreads();
        if (t == 0) atomicAdd(&g_done[lvl], 1);
    }
}

// ---------------- final reduction (fp32 partials, fp64 only per-CTA) ----------------
__device__ __forceinline__ float softplusf(float x) {
    return fmaxf(x, 0.f) + log1pf(expf(-fabsf(x)));
}

__global__ void reduce_kernel(const float* __restrict__ eval_w,
                              const float* __restrict__ eval_b,
                              const float* __restrict__ pos_vals,
                              const float* __restrict__ neg_vals)
{
    __shared__ float part[6];
    const int lane = threadIdx.x & 31;
    const int wid  = threadIdx.x >> 5;
    const int warpsPerBlock = blockDim.x >> 5;
    const int gw  = blockIdx.x * warpsPerBlock + wid;
    const int nw  = gridDim.x * warpsPerBlock;

    const float4 ew = ((const float4*)eval_w)[lane];
    const float  eb = eval_b[0];

    float a = 0, b = 0, sp = 0, sn = 0, pok = 0, nok = 0;
    for (int row = gw; row < N_TOT; row += nw) {
        float4 v = ((const float4*)(g_store + (size_t)row * D))[lane];
        float s = v.x * ew.x + v.y * ew.y + v.z * ew.z + v.w * ew.w;
        #pragma unroll
        for (int o = 16; o; o >>= 1) s += __shfl_xor_sync(0xffffffffu, s, o);
        if (lane == 0) {
            float logit = s + eb;
            float pv = pos_vals[row], nv = neg_vals[row];
            a  += pv * softplusf(-logit);
            b  += nv * softplusf(logit);
            sp += pv;
            sn += nv;
            if (logit >= 0.f) pok += pv; else nok += nv;
        }
    }
    if (threadIdx.x < 6) part[threadIdx.x] = 0.f;
    __syncthreads();
    if (lane == 0) {
        atomicAdd(&part[0], a);  atomicAdd(&part[1], b);
        atomicAdd(&part[2], sp); atomicAdd(&part[3], sn);
        atomicAdd(&part[4], pok); atomicAdd(&part[5], nok);
    }
    __syncthreads();
    if (threadIdx.x < 6) atomicAdd(&g_acc[threadIdx.x], (double)part[threadIdx.x]);
}

__global__ void finalize_kernel(float* out, int out_size)
{
    double A = g_acc[0], B = g_acc[1], P = g_acc[2], N = g_acc[3];
    double loss = (N / P) * A + B;
    if (out_size > 0) out[0] = (float)loss;
    if (out_size > 1) out[1] = (float)g_acc[4];
    if (out_size > 2) out[2] = (float)g_acc[5];
}

// ---------------- launch ----------------
extern "C" void kernel_launch(void* const* d_in, const int* in_sizes, int n_in,
                              void* d_out, int out_size)
{
    const float* thax_table = (const float*)d_in[0];
    const float* sine_table = (const float*)d_in[1];
    const float* rule_W     = (const float*)d_in[2];
    const float* rule_b     = (const float*)d_in[3];
    const float* eval_w     = (const float*)d_in[4];
    const float* eval_b     = (const float*)d_in[5];
    const float* pos_vals   = (const float*)d_in[6];
    const float* neg_vals   = (const float*)d_in[7];
    const int*   init_thax  = (const int*)d_in[8];
    const int*   init_sine  = (const int*)d_in[9];
    const int*   parents    = (const int*)d_in[10];
    const int*   rules      = (const int*)d_in[11];

    cudaFuncSetAttribute(level_persistent,
                         cudaFuncAttributeMaxDynamicSharedMemorySize, WSMEM);

    {   // axiom embeddings + counter reset
        int total = N_INIT * (D / 4);
        int blocks = (total + 255) / 256;
        init_kernel<<<blocks, 256>>>(thax_table, sine_table, init_thax, init_sine);
    }
    pack_kernel<<<N_RULES * 16, 512>>>(rule_W);
    bucket_kernel<<<LVLS, 256>>>(rules, parents);

    level_persistent<<<NCTA, 256, WSMEM>>>(rule_b, parents);

    reduce_kernel<<<1184, 256>>>(eval_w, eval_b, pos_vals, neg_vals);
    finalize_kernel<<<1, 1>>>((float*)d_out, out_size);
}

// round 7
// speedup vs baseline: 5.2613x; 1.1228x over previous
#include <cuda_runtime.h>
#include <cuda_bf16.h>
#include <cstdint>

#define D       128
#define TWOD    256
#define N_INIT  100000
#define LVLS    64
#define MM      4096
#define N_RULES 256
#define N_TOT   (N_INIT + LVLS * MM)

#define XS    264      // bf16 per sX row (256 + 8 pad, ldmatrix conflict-free)
#define NCTA  256      // persistent grid: one CTA per rule (all co-resident)
#define WSMEM 65536    // 64 KB packed W fragments per rule

// ---------------- device scratch (no allocations allowed) ----------------
__device__ float  g_store[(size_t)N_TOT * D];            // ~185 MB embeddings
__device__ double g_acc[8];
__device__ unsigned short g_lists[LVLS][MM];             // node ids bucketed by rule
__device__ int2           g_par2[LVLS][MM];              // parent ids, bucket order
__device__ int            g_offs[LVLS][N_RULES + 1];
__device__ int            g_maxlvl[LVLS][N_RULES];       // max parent level (-1 none)
__device__ uint2          g_Wfrag[(size_t)N_RULES * 16 * 16 * 32];  // 16 MB B-frags
__device__ int            g_done[LVLS];                  // CTAs finished per level

// ---------------- helpers ----------------
__device__ __forceinline__ uint32_t packbf(float lo, float hi) {
    __nv_bfloat162 h = __float22bfloat162_rn(make_float2(lo, hi));
    return *reinterpret_cast<uint32_t*>(&h);
}

__device__ __forceinline__ void mma_bf16(float c[4], uint32_t a0, uint32_t a1,
                                         uint32_t a2, uint32_t a3, uint2 b) {
    asm volatile(
        "mma.sync.aligned.m16n8k16.row.col.f32.bf16.bf16.f32 "
        "{%0,%1,%2,%3}, {%4,%5,%6,%7}, {%8,%9}, {%0,%1,%2,%3};"
        : "+f"(c[0]), "+f"(c[1]), "+f"(c[2]), "+f"(c[3])
        : "r"(a0), "r"(a1), "r"(a2), "r"(a3), "r"(b.x), "r"(b.y));
}

__device__ __forceinline__ int ld_acq(const int* addr) {
    int v;
    asm volatile("ld.acquire.gpu.global.b32 %0, [%1];" : "=r"(v) : "l"(addr) : "memory");
    return v;
}

__device__ __forceinline__ void red_release_add(int* addr) {
    asm volatile("red.release.gpu.global.add.s32 [%0], 1;" :: "l"(addr) : "memory");
}

// ---------------- init: axiom embeddings + zero counters ----------------
__global__ void init_kernel(const float* __restrict__ thax_table,
                            const float* __restrict__ sine_table,
                            const int*   __restrict__ init_thax,
                            const int*   __restrict__ init_sine)
{
    int idx = blockIdx.x * blockDim.x + threadIdx.x;
    if (blockIdx.x == 0 && threadIdx.x < 8)    g_acc[threadIdx.x] = 0.0;
    if (blockIdx.x == 0 && threadIdx.x < LVLS) g_done[threadIdx.x] = 0;
    int total = N_INIT * (D / 4);
    if (idx >= total) return;
    int n = idx >> 5;
    int q = idx & 31;
    const float4* ta = (const float4*)(thax_table + (size_t)init_thax[n] * D);
    const float4* sa = (const float4*)(sine_table + (size_t)init_sine[n] * D);
    float4 a = ta[q], b = sa[q], o;
    o.x = a.x + b.x; o.y = a.y + b.y; o.z = a.z + b.z; o.w = a.w + b.w;
    ((float4*)(g_store + (size_t)n * D))[q] = o;
}

// ---------------- one-time: pack W into mma B-fragment layout, bf16 ----------------
__global__ void pack_kernel(const float* __restrict__ rule_W)
{
    int rule  = blockIdx.x >> 4;
    int kstep = blockIdx.x & 15;
    int ntile = threadIdx.x >> 5;
    int lane  = threadIdx.x & 31;
    int k0 = kstep * 16 + (lane & 3) * 2;
    int n  = ntile * 8 + (lane >> 2);
    const float* base = rule_W + ((size_t)rule * TWOD + k0) * D + n;
    uint2 v;
    v.x = packbf(base[0],     base[D]);
    v.y = packbf(base[8 * D], base[9 * D]);
    g_Wfrag[(((size_t)rule * 16 + kstep) * 16 + ntile) * 32 + lane] = v;
}

// ---------------- bucket nodes by rule + parent ids + max parent level ----------------
__global__ void bucket_kernel(const int* __restrict__ rules,
                              const int* __restrict__ parents)
{
    __shared__ int hist[N_RULES];
    __shared__ int scan[N_RULES];
    __shared__ int cursor[N_RULES];
    __shared__ int maxp[N_RULES];
    const int lvl = blockIdx.x;
    const int t = threadIdx.x;     // 256 threads

    hist[t] = 0;
    maxp[t] = -1;
    __syncthreads();
    const int* lr = rules + lvl * MM;
    const int* lp = parents + (size_t)lvl * MM * 2;
    for (int m = t; m < MM; m += 256) {
        int r = lr[m];
        atomicAdd(&hist[r], 1);
        atomicMax(&maxp[r], max(lp[2 * m], lp[2 * m + 1]));
    }
    __syncthreads();

    scan[t] = hist[t];
    __syncthreads();
    for (int off = 1; off < N_RULES; off <<= 1) {
        int add = (t >= off) ? scan[t - off] : 0;
        __syncthreads();
        scan[t] += add;
        __syncthreads();
    }
    int excl = scan[t] - hist[t];
    g_offs[lvl][t] = excl;
    cursor[t] = excl;
    if (t == 0) g_offs[lvl][N_RULES] = MM;
    g_maxlvl[lvl][t] = (maxp[t] >= N_INIT) ? (maxp[t] - N_INIT) / MM : -1;
    __syncthreads();

    for (int m = t; m < MM; m += 256) {
        int r = lr[m];
        int p = atomicAdd(&cursor[r], 1);
        g_lists[lvl][p] = (unsigned short)m;
        g_par2[lvl][p]  = make_int2(lp[2 * m], lp[2 * m + 1]);
    }
}

// ---------------- persistent all-levels MLP, dataflow sync ----------------
// grid = 256 CTAs (one rule each), block = 256 (8 warps).
// Warp half h processes 16-node group with 4 ntiles (32 cols) per warp.
// Node/parent ids prefetched into smem BEFORE the dependency wait (static
// data) so the gather is a single global-latency hop after release.
__global__ __launch_bounds__(256)
void level_persistent(const float* __restrict__ rule_b)
{
    extern __shared__ uint2 sW[];                    // 64 KB
    __shared__ __nv_bfloat16 sX[2][16 * XS];         // 16.9 KB
    __shared__ int  sM[2][16];
    __shared__ int2 sP[2][16];

    const int rule = blockIdx.x;
    const int t = threadIdx.x, lane = t & 31, wid = t >> 5;

    // stage this rule's W fragments once
    {
        const uint4* src = (const uint4*)(g_Wfrag + (size_t)rule * (16 * 16 * 32));
        uint4* dst = (uint4*)sW;
        #pragma unroll 4
        for (int i = t; i < WSMEM / 16; i += 256) dst[i] = src[i];
    }

    const int wh  = wid >> 2;        // warp half (node group)
    const int wl  = wid & 3;         // warp-in-half
    const int nt0 = wl * 4;          // 4 ntiles -> 32 cols
    const int r0  = lane >> 2;
    float2 bs[4];
    int cols[4];
    #pragma unroll
    for (int j = 0; j < 4; j++) {
        cols[j] = (nt0 + j) * 8 + 2 * (lane & 3);
        bs[j] = *(const float2*)(rule_b + (size_t)rule * D + cols[j]);
    }
    const uint32_t arow = (uint32_t)__cvta_generic_to_shared(
        &sX[wh][(lane & 15) * XS + (lane >> 4) * 8]);

    for (int lvl = 0; lvl < LVLS; lvl++) {
        const int beg   = g_offs[lvl][rule];
        const int count = g_offs[lvl][rule + 1] - beg;
        const unsigned short* list = g_lists[lvl] + beg;
        float* outb = g_store + (size_t)(N_INIT + lvl * MM) * D;

        // prefetch ids for chunk 0 (static data — overlaps the wait below)
        if (t < 32) {
            int hh = t >> 4, sl = t & 15;
            bool ok = t < count;
            sM[hh][sl] = ok ? (int)list[t] : 0;
            sP[hh][sl] = ok ? g_par2[lvl][beg + t] : make_int2(0, 0);
        }

        // wait for the deepest parent level this (lvl, rule) references
        const int need = g_maxlvl[lvl][rule];
        if (need >= 0 && t == 0) {
            while (ld_acq(&g_done[need]) < NCTA) __nanosleep(16);
        }
        __syncthreads();

        for (int g0 = 0; g0 < count; g0 += 32) {
            if (g0 > 0) {   // rare (count > 32): load next chunk ids directly
                if (t < 32) {
                    int hh = t >> 4, sl = t & 15;
                    int idx = g0 + t;
                    bool ok = idx < count;
                    sM[hh][sl] = ok ? (int)list[idx] : 0;
                    sP[hh][sl] = ok ? g_par2[lvl][beg + idx] : make_int2(0, 0);
                }
                __syncthreads();
            }
            const int nodes_h = max(0, min(16, count - g0 - wh * 16));

            // ---- gather rows -> bf16 smem (one global hop, ids in smem) ----
            {
                int hh = t >> 7, tt = t & 127;
                int slot = tt >> 3, sub = tt & 7;
                int par = sub >> 2, seg = sub & 3;       // 32 floats per thread
                uint32_t tmp[16];
                if (g0 + hh * 16 + slot < count) {
                    int p = par ? sP[hh][slot].y : sP[hh][slot].x;
                    const float4* src = (const float4*)(g_store + (size_t)p * D + seg * 32);
                    #pragma unroll
                    for (int j = 0; j < 8; j++) {
                        float4 v = __ldcg(src + j);
                        tmp[2 * j]     = packbf(v.x, v.y);
                        tmp[2 * j + 1] = packbf(v.z, v.w);
                    }
                } else {
                    #pragma unroll
                    for (int j = 0; j < 16; j++) tmp[j] = 0u;
                }
                uint4* dst = (uint4*)(&sX[hh][slot * XS + par * 128 + seg * 32]);
                #pragma unroll
                for (int j = 0; j < 4; j++)
                    dst[j] = make_uint4(tmp[4*j], tmp[4*j+1], tmp[4*j+2], tmp[4*j+3]);
            }
            __syncthreads();

            // ---- warp: 16 k-steps of m16n8k16 over 4 ntiles ----
            float c[4][4];
            #pragma unroll
            for (int j = 0; j < 4; j++)
                #pragma unroll
                for (int q = 0; q < 4; q++) c[j][q] = 0.f;

            #pragma unroll 4
            for (int kt = 0; kt < 16; kt++) {
                uint32_t a0, a1, a2, a3;
                asm volatile(
                    "ldmatrix.sync.aligned.m8n8.x4.shared.b16 {%0,%1,%2,%3}, [%4];"
                    : "=r"(a0), "=r"(a1), "=r"(a2), "=r"(a3)
                    : "r"(arow + kt * 32));
                #pragma unroll
                for (int j = 0; j < 4; j++) {
                    uint2 b = sW[kt * 512 + (nt0 + j) * 32 + lane];
                    mma_bf16(c[j], a0, a1, a2, a3, b);
                }
            }

            // ---- epilogue: bias + ReLU + float2 scattered stores ----
            if (r0 < nodes_h) {
                int m = sM[wh][r0];
                float* row = outb + (size_t)m * D;
                #pragma unroll
                for (int j = 0; j < 4; j++) {
                    float2 o;
                    o.x = fmaxf(c[j][0] + bs[j].x, 0.f);
                    o.y = fmaxf(c[j][1] + bs[j].y, 0.f);
                    *(float2*)(row + cols[j]) = o;
                }
            }
            if (r0 + 8 < nodes_h) {
                int m = sM[wh][r0 + 8];
                float* row = outb + (size_t)m * D;
                #pragma unroll
                for (int j = 0; j < 4; j++) {
                    float2 o;
                    o.x = fmaxf(c[j][2] + bs[j].x, 0.f);
                    o.y = fmaxf(c[j][3] + bs[j].y, 0.f);
                    *(float2*)(row + cols[j]) = o;
                }
            }
            __syncthreads();
        }

        // publish completion (release after bar covers peer-thread stores)
        if (t == 0) red_release_add(&g_done[lvl]);
    }
}

// ---------------- final reduction (fp32 partials, fp64 per-CTA only) ----------------
__device__ __forceinline__ float softplusf(float x) {
    return fmaxf(x, 0.f) + log1pf(expf(-fabsf(x)));
}

__global__ void reduce_kernel(const float* __restrict__ eval_w,
                              const float* __restrict__ eval_b,
                              const float* __restrict__ pos_vals,
                              const float* __restrict__ neg_vals)
{
    __shared__ float part[6];
    const int lane = threadIdx.x & 31;
    const int wid  = threadIdx.x >> 5;
    const int warpsPerBlock = blockDim.x >> 5;
    const int gw  = blockIdx.x * warpsPerBlock + wid;
    const int nw  = gridDim.x * warpsPerBlock;

    const float4 ew = ((const float4*)eval_w)[lane];
    const float  eb = eval_b[0];

    float a = 0, b = 0, sp = 0, sn = 0, pok = 0, nok = 0;
    for (int row = gw; row < N_TOT; row += nw) {
        float4 v = ((const float4*)(g_store + (size_t)row * D))[lane];
        float s = v.x * ew.x + v.y * ew.y + v.z * ew.z + v.w * ew.w;
        #pragma unroll
        for (int o = 16; o; o >>= 1) s += __shfl_xor_sync(0xffffffffu, s, o);
        if (lane == 0) {
            float logit = s + eb;
            float pv = pos_vals[row], nv = neg_vals[row];
            a  += pv * softplusf(-logit);
            b  += nv * softplusf(logit);
            sp += pv;
            sn += nv;
            if (logit >= 0.f) pok += pv; else nok += nv;
        }
    }
    if (threadIdx.x < 6) part[threadIdx.x] = 0.f;
    __syncthreads();
    if (lane == 0) {
        atomicAdd(&part[0], a);  atomicAdd(&part[1], b);
        atomicAdd(&part[2], sp); atomicAdd(&part[3], sn);
        atomicAdd(&part[4], pok); atomicAdd(&part[5], nok);
    }
    __syncthreads();
    if (threadIdx.x < 6) atomicAdd(&g_acc[threadIdx.x], (double)part[threadIdx.x]);
}

__global__ void finalize_kernel(float* out, int out_size)
{
    double A = g_acc[0], B = g_acc[1], P = g_acc[2], N = g_acc[3];
    double loss = (N / P) * A + B;
    if (out_size > 0) out[0] = (float)loss;
    if (out_size > 1) out[1] = (float)g_acc[4];
    if (out_size > 2) out[2] = (float)g_acc[5];
}

// ---------------- launch ----------------
extern "C" void kernel_launch(void* const* d_in, const int* in_sizes, int n_in,
                              void* d_out, int out_size)
{
    const float* thax_table = (const float*)d_in[0];
    const float* sine_table = (const float*)d_in[1];
    const float* rule_W     = (const float*)d_in[2];
    const float* rule_b     = (const float*)d_in[3];
    const float* eval_w     = (const float*)d_in[4];
    const float* eval_b     = (const float*)d_in[5];
    const float* pos_vals   = (const float*)d_in[6];
    const float* neg_vals   = (const float*)d_in[7];
    const int*   init_thax  = (const int*)d_in[8];
    const int*   init_sine  = (const int*)d_in[9];
    const int*   parents    = (const int*)d_in[10];
    const int*   rules      = (const int*)d_in[11];

    cudaFuncSetAttribute(level_persistent,
                         cudaFuncAttributeMaxDynamicSharedMemorySize, WSMEM);

    {   // axiom embeddings + counter reset
        int total = N_INIT * (D / 4);
        int blocks = (total + 255) / 256;
        init_kernel<<<blocks, 256>>>(thax_table, sine_table, init_thax, init_sine);
    }
    pack_kernel<<<N_RULES * 16, 512>>>(rule_W);
    bucket_kernel<<<LVLS, 256>>>(rules, parents);

    level_persistent<<<NCTA, 256, WSMEM>>>(rule_b);

    reduce_kernel<<<1184, 256>>>(eval_w, eval_b, pos_vals, neg_vals);
    finalize_kernel<<<1, 1>>>((float*)d_out, out_size);
}

// round 8
// speedup vs baseline: 5.9558x; 1.1320x over previous
#include <cuda_runtime.h>
#include <cuda_bf16.h>
#include <cstdint>

#define D       128
#define TWOD    256
#define N_INIT  100000
#define LVLS    64
#define MM      4096
#define N_RULES 256
#define N_TOT   (N_INIT + LVLS * MM)

#define XS    264      // bf16 per sX row (256 + 8 pad, ldmatrix conflict-free)
#define NCTA  256      // persistent grid: one CTA per rule (all co-resident)
#define WSMEM 65536    // 64 KB packed W fragments per rule

// ---------------- device scratch (no allocations allowed) ----------------
__device__ float  g_store[(size_t)N_TOT * D];            // ~185 MB embeddings
__device__ float  g_logit[N_TOT];                        // fused eval-net logits (no +eb)
__device__ double g_acc[8];
__device__ unsigned short g_lists[LVLS][MM];             // node ids bucketed by rule
__device__ int2           g_par2[LVLS][MM];              // parent ids, bucket order
__device__ int            g_offs[LVLS][N_RULES + 1];
__device__ int            g_maxlvl[LVLS][N_RULES];       // max parent level (-1 none)
__device__ uint2          g_Wfrag[(size_t)N_RULES * 16 * 16 * 32];  // 16 MB B-frags
__device__ int            g_done[LVLS];                  // CTAs finished per level

// ---------------- helpers ----------------
__device__ __forceinline__ uint32_t packbf(float lo, float hi) {
    __nv_bfloat162 h = __float22bfloat162_rn(make_float2(lo, hi));
    return *reinterpret_cast<uint32_t*>(&h);
}

__device__ __forceinline__ void mma_bf16(float c[4], uint32_t a0, uint32_t a1,
                                         uint32_t a2, uint32_t a3, uint2 b) {
    asm volatile(
        "mma.sync.aligned.m16n8k16.row.col.f32.bf16.bf16.f32 "
        "{%0,%1,%2,%3}, {%4,%5,%6,%7}, {%8,%9}, {%0,%1,%2,%3};"
        : "+f"(c[0]), "+f"(c[1]), "+f"(c[2]), "+f"(c[3])
        : "r"(a0), "r"(a1), "r"(a2), "r"(a3), "r"(b.x), "r"(b.y));
}

__device__ __forceinline__ int ld_acq(const int* addr) {
    int v;
    asm volatile("ld.acquire.gpu.global.b32 %0, [%1];" : "=r"(v) : "l"(addr) : "memory");
    return v;
}

__device__ __forceinline__ void red_release_add(int* addr) {
    asm volatile("red.release.gpu.global.add.s32 [%0], 1;" :: "l"(addr) : "memory");
}

// ---------------- init: axiom embeddings + logits + zero counters ----------------
__global__ void init_kernel(const float* __restrict__ thax_table,
                            const float* __restrict__ sine_table,
                            const int*   __restrict__ init_thax,
                            const int*   __restrict__ init_sine,
                            const float* __restrict__ eval_w)
{
    int idx = blockIdx.x * blockDim.x + threadIdx.x;
    if (blockIdx.x == 0 && threadIdx.x < 8)    g_acc[threadIdx.x] = 0.0;
    if (blockIdx.x == 0 && threadIdx.x < LVLS) g_done[threadIdx.x] = 0;
    if (idx < LVLS * MM) g_logit[N_INIT + idx] = 0.f;     // derived logits accumulate
    int total = N_INIT * (D / 4);
    if (idx >= total) return;
    int n = idx >> 5;          // one warp == one row (blockDim multiple of 32)
    int q = idx & 31;
    const float4* ta = (const float4*)(thax_table + (size_t)init_thax[n] * D);
    const float4* sa = (const float4*)(sine_table + (size_t)init_sine[n] * D);
    float4 a = ta[q], b = sa[q], o;
    o.x = a.x + b.x; o.y = a.y + b.y; o.z = a.z + b.z; o.w = a.w + b.w;
    ((float4*)(g_store + (size_t)n * D))[q] = o;
    // fused axiom logit
    float4 ew = ((const float4*)eval_w)[q];
    float s = o.x * ew.x + o.y * ew.y + o.z * ew.z + o.w * ew.w;
    #pragma unroll
    for (int off = 16; off; off >>= 1) s += __shfl_xor_sync(0xffffffffu, s, off);
    if (q == 0) g_logit[n] = s;
}

// ---------------- one-time: pack W into mma B-fragment layout, bf16 ----------------
__global__ void pack_kernel(const float* __restrict__ rule_W)
{
    int rule  = blockIdx.x >> 4;
    int kstep = blockIdx.x & 15;
    int ntile = threadIdx.x >> 5;
    int lane  = threadIdx.x & 31;
    int k0 = kstep * 16 + (lane & 3) * 2;
    int n  = ntile * 8 + (lane >> 2);
    const float* base = rule_W + ((size_t)rule * TWOD + k0) * D + n;
    uint2 v;
    v.x = packbf(base[0],     base[D]);
    v.y = packbf(base[8 * D], base[9 * D]);
    g_Wfrag[(((size_t)rule * 16 + kstep) * 16 + ntile) * 32 + lane] = v;
}

// ---------------- bucket nodes by rule + parent ids + max parent level ----------------
__global__ void bucket_kernel(const int* __restrict__ rules,
                              const int* __restrict__ parents)
{
    __shared__ int hist[N_RULES];
    __shared__ int scan[N_RULES];
    __shared__ int cursor[N_RULES];
    __shared__ int maxp[N_RULES];
    const int lvl = blockIdx.x;
    const int t = threadIdx.x;     // 256 threads

    hist[t] = 0;
    maxp[t] = -1;
    __syncthreads();
    const int* lr = rules + lvl * MM;
    const int* lp = parents + (size_t)lvl * MM * 2;
    for (int m = t; m < MM; m += 256) {
        int r = lr[m];
        atomicAdd(&hist[r], 1);
        atomicMax(&maxp[r], max(lp[2 * m], lp[2 * m + 1]));
    }
    __syncthreads();

    scan[t] = hist[t];
    __syncthreads();
    for (int off = 1; off < N_RULES; off <<= 1) {
        int add = (t >= off) ? scan[t - off] : 0;
        __syncthreads();
        scan[t] += add;
        __syncthreads();
    }
    int excl = scan[t] - hist[t];
    g_offs[lvl][t] = excl;
    cursor[t] = excl;
    if (t == 0) g_offs[lvl][N_RULES] = MM;
    g_maxlvl[lvl][t] = (maxp[t] >= N_INIT) ? (maxp[t] - N_INIT) / MM : -1;
    __syncthreads();

    for (int m = t; m < MM; m += 256) {
        int r = lr[m];
        int p = atomicAdd(&cursor[r], 1);
        g_lists[lvl][p] = (unsigned short)m;
        g_par2[lvl][p]  = make_int2(lp[2 * m], lp[2 * m + 1]);
    }
}

// ---------------- persistent all-levels MLP, split-phase dataflow ----------------
// grid = 256 CTAs (one rule each), block = 256 (8 warps).
// Chunk 0 gather is split: parents below the waited level are gathered while
// the dependency is in flight; only level-`need` rows gather after release.
__global__ __launch_bounds__(256)
void level_persistent(const float* __restrict__ rule_b,
                      const float* __restrict__ eval_w)
{
    extern __shared__ uint2 sW[];                    // 64 KB
    __shared__ __nv_bfloat16 sX[2][16 * XS];         // 16.9 KB
    __shared__ int  sM[2][16];
    __shared__ int2 sP[2][16];

    const int rule = blockIdx.x;
    const int t = threadIdx.x, lane = t & 31, wid = t >> 5;

    // stage this rule's W fragments once
    {
        const uint4* src = (const uint4*)(g_Wfrag + (size_t)rule * (16 * 16 * 32));
        uint4* dst = (uint4*)sW;
        #pragma unroll 4
        for (int i = t; i < WSMEM / 16; i += 256) dst[i] = src[i];
    }

    const int wh  = wid >> 2;        // warp half (node group)
    const int wl  = wid & 3;         // warp-in-half
    const int nt0 = wl * 4;          // 4 ntiles -> 32 cols
    const int r0  = lane >> 2;
    float2 bs[4], ewv[4];
    int cols[4];
    #pragma unroll
    for (int j = 0; j < 4; j++) {
        cols[j] = (nt0 + j) * 8 + 2 * (lane & 3);
        bs[j]  = *(const float2*)(rule_b + (size_t)rule * D + cols[j]);
        ewv[j] = *(const float2*)(eval_w + cols[j]);
    }
    const uint32_t arow = (uint32_t)__cvta_generic_to_shared(
        &sX[wh][(lane & 15) * XS + (lane >> 4) * 8]);

    // gather thread mapping (fixed): 2 threads per (slot, parent) pair
    const int g_hh   = t >> 7;          // which 16-node group
    const int g_tt   = t & 127;
    const int g_slot = g_tt >> 3;
    const int g_par  = (g_tt >> 2) & 1;
    const int g_seg  = g_tt & 3;        // 32 floats per thread

    for (int lvl = 0; lvl < LVLS; lvl++) {
        const int beg   = g_offs[lvl][rule];
        const int count = g_offs[lvl][rule + 1] - beg;
        const unsigned short* list = g_lists[lvl] + beg;
        float* outb = g_store + (size_t)(N_INIT + lvl * MM) * D;
        const int need = g_maxlvl[lvl][rule];
        const int TH = N_INIT + need * MM;   // parents >= TH are at level `need`

        // prefetch chunk-0 ids (static data)
        if (t < 32) {
            int hh = t >> 4, sl = t & 15;
            bool ok = t < count;
            sM[hh][sl] = ok ? (int)list[t] : 0;
            sP[hh][sl] = ok ? g_par2[lvl][beg + t] : make_int2(0, 0);
        }
        // pre-wait: everything strictly below `need` is complete after this
        if (need >= 1 && t == 0) {
            while (ld_acq(&g_done[need - 1]) < NCTA) {}
        }
        __syncthreads();

        for (int g0 = 0; g0 < count; g0 += 32) {
            if (g0 > 0) {   // rare: later chunks, ids + plain gather (deps done)
                if (t < 32) {
                    int hh = t >> 4, sl = t & 15;
                    int idx = g0 + t;
                    bool ok = idx < count;
                    sM[hh][sl] = ok ? (int)list[idx] : 0;
                    sP[hh][sl] = ok ? g_par2[lvl][beg + idx] : make_int2(0, 0);
                }
                __syncthreads();
            }
            const int nodes_h = max(0, min(16, count - g0 - wh * 16));
            const bool inrange = (g0 + g_hh * 16 + g_slot) < count;
            const int p_my = g_par ? sP[g_hh][g_slot].y : sP[g_hh][g_slot].x;
            const bool early = (g0 > 0) || (p_my < TH);

            // ---- phase 1: early gather (overlaps the dependency wait) ----
            if (inrange && early) {
                const float4* src = (const float4*)(g_store + (size_t)p_my * D + g_seg * 32);
                uint32_t tmp[16];
                #pragma unroll
                for (int j = 0; j < 8; j++) {
                    float4 v = __ldcg(src + j);
                    tmp[2 * j]     = packbf(v.x, v.y);
                    tmp[2 * j + 1] = packbf(v.z, v.w);
                }
                uint4* dst = (uint4*)(&sX[g_hh][g_slot * XS + g_par * 128 + g_seg * 32]);
                #pragma unroll
                for (int j = 0; j < 4; j++)
                    dst[j] = make_uint4(tmp[4*j], tmp[4*j+1], tmp[4*j+2], tmp[4*j+3]);
            } else if (!inrange) {
                uint4* dst = (uint4*)(&sX[g_hh][g_slot * XS + g_par * 128 + g_seg * 32]);
                #pragma unroll
                for (int j = 0; j < 4; j++) dst[j] = make_uint4(0u, 0u, 0u, 0u);
            }

            // ---- the real dependency wait (first chunk only) ----
            if (g0 == 0 && need >= 0 && t == 0) {
                while (ld_acq(&g_done[need]) < NCTA) {}
            }
            __syncthreads();

            // ---- phase 2: late gather (few rows at level `need`) ----
            if (inrange && !early) {
                const float4* src = (const float4*)(g_store + (size_t)p_my * D + g_seg * 32);
                uint32_t tmp[16];
                #pragma unroll
                for (int j = 0; j < 8; j++) {
                    float4 v = __ldcg(src + j);
                    tmp[2 * j]     = packbf(v.x, v.y);
                    tmp[2 * j + 1] = packbf(v.z, v.w);
                }
                uint4* dst = (uint4*)(&sX[g_hh][g_slot * XS + g_par * 128 + g_seg * 32]);
                #pragma unroll
                for (int j = 0; j < 4; j++)
                    dst[j] = make_uint4(tmp[4*j], tmp[4*j+1], tmp[4*j+2], tmp[4*j+3]);
            }
            __syncthreads();

            // ---- warp: 16 k-steps of m16n8k16 over 4 ntiles ----
            float c[4][4];
            #pragma unroll
            for (int j = 0; j < 4; j++)
                #pragma unroll
                for (int q = 0; q < 4; q++) c[j][q] = 0.f;

            #pragma unroll 4
            for (int kt = 0; kt < 16; kt++) {
                uint32_t a0, a1, a2, a3;
                asm volatile(
                    "ldmatrix.sync.aligned.m8n8.x4.shared.b16 {%0,%1,%2,%3}, [%4];"
                    : "=r"(a0), "=r"(a1), "=r"(a2), "=r"(a3)
                    : "r"(arow + kt * 32));
                #pragma unroll
                for (int j = 0; j < 4; j++) {
                    uint2 b = sW[kt * 512 + (nt0 + j) * 32 + lane];
                    mma_bf16(c[j], a0, a1, a2, a3, b);
                }
            }

            // ---- epilogue: bias + ReLU + stores + fused logit partials ----
            float lp0 = 0.f, lp1 = 0.f;
            int m0 = sM[wh][r0], m1 = sM[wh][r0 + 8];
            if (r0 < nodes_h) {
                float* row = outb + (size_t)m0 * D;
                #pragma unroll
                for (int j = 0; j < 4; j++) {
                    float2 o;
                    o.x = fmaxf(c[j][0] + bs[j].x, 0.f);
                    o.y = fmaxf(c[j][1] + bs[j].y, 0.f);
                    *(float2*)(row + cols[j]) = o;
                    lp0 += o.x * ewv[j].x + o.y * ewv[j].y;
                }
            }
            if (r0 + 8 < nodes_h) {
                float* row = outb + (size_t)m1 * D;
                #pragma unroll
                for (int j = 0; j < 4; j++) {
                    float2 o;
                    o.x = fmaxf(c[j][2] + bs[j].x, 0.f);
                    o.y = fmaxf(c[j][3] + bs[j].y, 0.f);
                    *(float2*)(row + cols[j]) = o;
                    lp1 += o.x * ewv[j].x + o.y * ewv[j].y;
                }
            }
            // quad-reduce logit partials (lanes 4r+0..3 share a node)
            lp0 += __shfl_down_sync(0xffffffffu, lp0, 2, 4);
            lp0 += __shfl_down_sync(0xffffffffu, lp0, 1, 4);
            lp1 += __shfl_down_sync(0xffffffffu, lp1, 2, 4);
            lp1 += __shfl_down_sync(0xffffffffu, lp1, 1, 4);
            if ((lane & 3) == 0) {
                if (r0 < nodes_h)     atomicAdd(&g_logit[N_INIT + lvl * MM + m0], lp0);
                if (r0 + 8 < nodes_h) atomicAdd(&g_logit[N_INIT + lvl * MM + m1], lp1);
            }
            __syncthreads();
        }

        // publish completion (release after bar covers peer-thread stores)
        if (t == 0) red_release_add(&g_done[lvl]);
    }
}

// ---------------- final reduction over fused logits (4.3 MB) ----------------
__device__ __forceinline__ float softplusf(float x) {
    return fmaxf(x, 0.f) + log1pf(expf(-fabsf(x)));
}

__global__ void reduce_kernel(const float* __restrict__ eval_b,
                              const float* __restrict__ pos_vals,
                              const float* __restrict__ neg_vals)
{
    __shared__ float part[6];
    const float eb = eval_b[0];
    const int stride = gridDim.x * blockDim.x;
    int i = blockIdx.x * blockDim.x + threadIdx.x;

    float a = 0, b = 0, sp = 0, sn = 0, pok = 0, nok = 0;
    for (int row = i; row < N_TOT; row += stride) {
        float logit = g_logit[row] + eb;
        float pv = pos_vals[row], nv = neg_vals[row];
        a  += pv * softplusf(-logit);
        b  += nv * softplusf(logit);
        sp += pv;
        sn += nv;
        if (logit >= 0.f) pok += pv; else nok += nv;
    }
    // warp reduce
    #pragma unroll
    for (int o = 16; o; o >>= 1) {
        a  += __shfl_xor_sync(0xffffffffu, a, o);
        b  += __shfl_xor_sync(0xffffffffu, b, o);
        sp += __shfl_xor_sync(0xffffffffu, sp, o);
        sn += __shfl_xor_sync(0xffffffffu, sn, o);
        pok += __shfl_xor_sync(0xffffffffu, pok, o);
        nok += __shfl_xor_sync(0xffffffffu, nok, o);
    }
    if (threadIdx.x < 6) part[threadIdx.x] = 0.f;
    __syncthreads();
    if ((threadIdx.x & 31) == 0) {
        atomicAdd(&part[0], a);  atomicAdd(&part[1], b);
        atomicAdd(&part[2], sp); atomicAdd(&part[3], sn);
        atomicAdd(&part[4], pok); atomicAdd(&part[5], nok);
    }
    __syncthreads();
    if (threadIdx.x < 6) atomicAdd(&g_acc[threadIdx.x], (double)part[threadIdx.x]);
}

__global__ void finalize_kernel(float* out, int out_size)
{
    double A = g_acc[0], B = g_acc[1], P = g_acc[2], N = g_acc[3];
    double loss = (N / P) * A + B;
    if (out_size > 0) out[0] = (float)loss;
    if (out_size > 1) out[1] = (float)g_acc[4];
    if (out_size > 2) out[2] = (float)g_acc[5];
}

// ---------------- launch ----------------
extern "C" void kernel_launch(void* const* d_in, const int* in_sizes, int n_in,
                              void* d_out, int out_size)
{
    const float* thax_table = (const float*)d_in[0];
    const float* sine_table = (const float*)d_in[1];
    const float* rule_W     = (const float*)d_in[2];
    const float* rule_b     = (const float*)d_in[3];
    const float* eval_w     = (const float*)d_in[4];
    const float* eval_b     = (const float*)d_in[5];
    const float* pos_vals   = (const float*)d_in[6];
    const float* neg_vals   = (const float*)d_in[7];
    const int*   init_thax  = (const int*)d_in[8];
    const int*   init_sine  = (const int*)d_in[9];
    const int*   parents    = (const int*)d_in[10];
    const int*   rules      = (const int*)d_in[11];

    cudaFuncSetAttribute(level_persistent,
                         cudaFuncAttributeMaxDynamicSharedMemorySize, WSMEM);

    {   // axiom embeddings + logits + counter reset
        int total = N_INIT * (D / 4);
        int blocks = (total + 255) / 256;
        init_kernel<<<blocks, 256>>>(thax_table, sine_table, init_thax, init_sine, eval_w);
    }
    pack_kernel<<<N_RULES * 16, 512>>>(rule_W);
    bucket_kernel<<<LVLS, 256>>>(rules, parents);

    level_persistent<<<NCTA, 256, WSMEM>>>(rule_b, eval_w);

    reduce_kernel<<<592, 256>>>(eval_b, pos_vals, neg_vals);
    finalize_kernel<<<1, 1>>>((float*)d_out, out_size);
}